// round 14
// baseline (speedup 1.0000x reference)
#include <cuda_runtime.h>
#include <cuda_bf16.h>
#include <cuda_fp16.h>
#include <math.h>
#include <stdint.h>

// ---------------- constants ----------------
#define kB 2
#define kT 1024
#define kD 1024
#define kDFF 4096
#define kV 32000
#define kL 12
#define kN (kB * kT)  // 2048 rows

typedef __nv_bfloat16 bf16;

// ---------------- scratch ----------------
__device__ float g_x[kN * kD];
__device__ float g_rkv[kN * 3 * kD];
__device__ float g_att[kN * kD];
__device__ float g_elog[(size_t)kN * kV];     // exit logits stored as fp16 (aliased)
__device__ __half g_h1[kN * kD];              // fp16 single A (all GEMM inputs)
__device__ __half g_ff2h[(size_t)kN * kDFF];  // fp16 single A for Wocm (silu output)
// weights: ALL single-term fp16 K'=K. W12 rows interleaved W1/W2.
__device__ __half g_Wrkvh[(size_t)kL * 3 * kD * kD];
__device__ __half g_Wotmh[(size_t)kL * kD * kD];
__device__ __half g_W123h[(size_t)kL * 2 * kDFF * kD];
__device__ __half g_Wocmh[(size_t)kL * kD * kDFF];
__device__ __half g_embedh[(size_t)kV * kD];
__device__ __half g_exith[(size_t)2 * kV * kD];

__device__ double g_gn_part[kB][128][2];
__device__ float g_hbar[kB * kD];
__device__ float g_conf[2 * kB];
__device__ float g_lse_f[kN], g_tgt_f[kN];
__device__ int   g_amax_f[kN];
__device__ float g_lse_e[2 * kN], g_tgt_e[2 * kN], g_ent_e[2 * kN];
__device__ int   g_amax_e[2 * kN];

// ---------------- helpers ----------------
__device__ __forceinline__ uint32_t smem_u32(const void* p) {
  return (uint32_t)__cvta_generic_to_shared(p);
}
__device__ __forceinline__ void cp16(uint32_t s, const void* g) {
  asm volatile("cp.async.ca.shared.global [%0], [%1], 16;\n" ::"r"(s), "l"(g));
}
__device__ __forceinline__ void cp_commit() { asm volatile("cp.async.commit_group;\n"); }
template <int NW>
__device__ __forceinline__ void cp_wait() { asm volatile("cp.async.wait_group %0;\n" ::"n"(NW)); }
__device__ __forceinline__ void ldm_x4(uint32_t* r, uint32_t a) {
  asm volatile("ldmatrix.sync.aligned.m8n8.x4.shared.b16 {%0,%1,%2,%3}, [%4];\n"
               : "=r"(r[0]), "=r"(r[1]), "=r"(r[2]), "=r"(r[3]) : "r"(a));
}
__device__ __forceinline__ void mma_f16(float* d, const uint32_t* a, const uint32_t* b) {
  asm volatile(
      "mma.sync.aligned.m16n8k16.row.col.f32.f16.f16.f32 "
      "{%0,%1,%2,%3}, {%4,%5,%6,%7}, {%8,%9}, {%0,%1,%2,%3};\n"
      : "+f"(d[0]), "+f"(d[1]), "+f"(d[2]), "+f"(d[3])
      : "r"(a[0]), "r"(a[1]), "r"(a[2]), "r"(a[3]), "r"(b[0]), "r"(b[1]));
}

// ---------------- segmented weight conversion ----------------
struct ConvSeg {
  const float* in;
  void* out;
  int K;
  int srcRPL;
  int outRPL;
  int outOff;
  int fmt;      // 2 = single-term fp16
  int rstride;  // output row spacing (2 = interleave)
  long cum;     // cumulative END (in float4 units)
};
struct ConvArgs { ConvSeg s[4]; };

__global__ void conv_multi(ConvArgs a, long grand) {
  long i = (long)blockIdx.x * blockDim.x + threadIdx.x;
  if (i >= grand) return;
  int si = 0;
  while (i >= a.s[si].cum) si++;
  long local = i - (si ? a.s[si - 1].cum : 0L);
  const ConvSeg g = a.s[si];
  int K4 = g.K >> 2;
  long rs = local / K4;
  int c = (int)(local % K4) << 2;
  long layer = rs / g.srcRPL;
  int r = (int)(rs % g.srcRPL);
  long orow = layer * g.outRPL + g.outOff + (long)r * g.rstride;
  float4 v = ((const float4*)g.in)[local];
  float vv[4] = {v.x, v.y, v.z, v.w};
  ushort h[4];
#pragma unroll
  for (int e = 0; e < 4; e++) h[e] = __half_as_ushort(__float2half_rn(vv[e]));
  uint2 hp = {(uint32_t)h[0] | ((uint32_t)h[1] << 16), (uint32_t)h[2] | ((uint32_t)h[3] << 16)};
  __half* ob = (__half*)g.out + orow * (long)g.K;
  *(uint2*)(ob + c) = hp;
}

// ---------------- pipelined fp16 tensor-core GEMM ----------------
// C[n,m] = sum_k A[n,k]*W[m,k], fp16 operands, fp32 accum.
// MODE 0: store fp32. 1: sigmoid where col<sigcut else store (fp32).
// MODE 2: += C (fp32). MODE 3: fused SwiGLU -> fp16 at col gc/2 (M=kDFF).
// MODE 4: store fp16.
#define BM 128
#define BN 128
#define BK 32
#define NST 3
#define LDSB 80  // bytes per smem row (40 elems)
#define STAGE_B ((BM + BN) * LDSB)  // 20480

template <int MODE>
__global__ void __launch_bounds__(256, 2)
gemm3(const __half* __restrict__ A, const __half* __restrict__ W,
      float* __restrict__ C, int M, int Kp, int sigcut) {
  extern __shared__ bf16 dynsmem[];
  uint32_t sbase = smem_u32(dynsmem);

  int tid = threadIdx.x;
  int lane = tid & 31, wid = tid >> 5;
  int wm = wid >> 2, wn = wid & 3;  // 2x4 warps, warp tile 64x32

  const __half* Ab = A + (size_t)(blockIdx.x * BM) * Kp;
  const __half* Wb = W + (size_t)(blockIdx.y * BN) * Kp;

  int r0 = tid >> 2, c0 = (tid & 3);
  int r1 = (tid + 256) >> 2, c1 = (tid & 3);

  float acc[4][4][4];
#pragma unroll
  for (int i = 0; i < 4; i++)
#pragma unroll
    for (int j = 0; j < 4; j++)
#pragma unroll
      for (int q = 0; q < 4; q++) acc[i][j][q] = 0.f;

  int KT = Kp / BK;

  int laneA = (wm * 64 + (lane & 7) + ((lane >> 3) & 1) * 8) * LDSB + ((lane >> 4)) * 16;
  int laneW = BM * LDSB + (wn * 32 + (lane & 7) + (lane >> 4) * 8) * LDSB +
              (((lane >> 3) & 1)) * 16;

#define ISSUE(stage, kt)                                                            \
  {                                                                                 \
    uint32_t sb = sbase + (uint32_t)(stage) * STAGE_B;                              \
    const __half* ga = Ab + (size_t)(kt) * BK;                                      \
    const __half* gw = Wb + (size_t)(kt) * BK;                                      \
    cp16(sb + r0 * LDSB + c0 * 16, ga + (size_t)r0 * Kp + c0 * 8);                  \
    cp16(sb + r1 * LDSB + c1 * 16, ga + (size_t)r1 * Kp + c1 * 8);                  \
    cp16(sb + BM * LDSB + r0 * LDSB + c0 * 16, gw + (size_t)r0 * Kp + c0 * 8);      \
    cp16(sb + BM * LDSB + r1 * LDSB + c1 * 16, gw + (size_t)r1 * Kp + c1 * 8);      \
  }

  ISSUE(0, 0); cp_commit();
  ISSUE(1, 1); cp_commit();

  for (int kt = 0; kt < KT; kt++) {
    cp_wait<1>();
    __syncthreads();
    int st = kt % NST;
    if (kt + 2 < KT) { ISSUE((kt + 2) % NST, kt + 2); }
    cp_commit();

    uint32_t stA = sbase + st * STAGE_B + laneA;
    uint32_t stW = sbase + st * STAGE_B + laneW;
#pragma unroll
    for (int kk = 0; kk < 2; kk++) {
      uint32_t b[8];
      ldm_x4(b, stW + kk * 32);
      ldm_x4(b + 4, stW + 16 * LDSB + kk * 32);
#pragma unroll
      for (int mt = 0; mt < 4; mt++) {
        uint32_t a[4];
        ldm_x4(a, stA + mt * 16 * LDSB + kk * 32);
#pragma unroll
        for (int nt = 0; nt < 4; nt++) mma_f16(acc[mt][nt], a, b + nt * 2);
      }
    }
  }
#undef ISSUE

  // epilogue
#pragma unroll
  for (int mt = 0; mt < 4; mt++) {
#pragma unroll
    for (int nt = 0; nt < 4; nt++) {
      int gr0 = blockIdx.x * BM + wm * 64 + mt * 16 + (lane >> 2);
      int gc = blockIdx.y * BN + wn * 32 + nt * 8 + ((lane & 3) << 1);
#pragma unroll
      for (int half = 0; half < 2; half++) {
        int gr = gr0 + half * 8;
        float v0 = acc[mt][nt][half * 2 + 0];
        float v1 = acc[mt][nt][half * 2 + 1];
        if (MODE == 3) {
          float y = (v0 / (1.f + expf(-v0))) * v1;
          __half* oh = (__half*)C;
          oh[(size_t)gr * M + (gc >> 1)] = __float2half_rn(y);
        } else if (MODE == 4) {
          __half* oh = (__half*)C;
          size_t off = (size_t)gr * M + gc;
          oh[off] = __float2half_rn(v0);
          oh[off + 1] = __float2half_rn(v1);
        } else {
          size_t off = (size_t)gr * M + gc;
          if (MODE == 1) {
            if (gc < sigcut) {
              v0 = 1.f / (1.f + expf(-v0));
              v1 = 1.f / (1.f + expf(-v1));
            }
          } else if (MODE == 2) {
            float2 old = *(const float2*)&C[off];
            v0 += old.x; v1 += old.y;
          }
          float2 o2 = {v0, v1};
          *(float2*)&C[off] = o2;
        }
      }
    }
  }
}

// ---------------- LayerNorm ----------------
__device__ __forceinline__ void ln_stats(const float* __restrict__ x, float& mean,
                                         float& rstd) {
  int tid = threadIdx.x;
  float s = 0.f, ss = 0.f;
  for (int i = tid; i < kD; i += 256) { float v = x[i]; s += v; ss += v * v; }
  __shared__ float shs[32], shss[32];
  for (int off = 16; off; off >>= 1) {
    s += __shfl_down_sync(0xffffffffu, s, off);
    ss += __shfl_down_sync(0xffffffffu, ss, off);
  }
  if ((tid & 31) == 0) { shs[tid >> 5] = s; shss[tid >> 5] = ss; }
  __syncthreads();
  if (tid < 32) {
    s = tid < 8 ? shs[tid] : 0.f;
    ss = tid < 8 ? shss[tid] : 0.f;
    for (int off = 4; off; off >>= 1) {
      s += __shfl_down_sync(0xffffffffu, s, off);
      ss += __shfl_down_sync(0xffffffffu, ss, off);
    }
    if (tid == 0) { shs[0] = s; shss[0] = ss; }
  }
  __syncthreads();
  mean = shs[0] / (float)kD;
  float var = shss[0] / (float)kD - mean * mean;
  rstd = rsqrtf(var + 1e-5f);
}

__global__ void ln_rows1h(const float* __restrict__ in, __half* __restrict__ out1,
                          const float* __restrict__ w, const float* __restrict__ bb) {
  size_t row = blockIdx.x;
  const float* x = in + row * kD;
  float mean, rstd;
  ln_stats(x, mean, rstd);
  __half* ob = out1 + row * kD;
  for (int i = threadIdx.x; i < kD; i += 256) {
    float y = (x[i] - mean) * rstd * w[i] + bb[i];
    ob[i] = __float2half_rn(y);
  }
}

__global__ void embed_ln(const int* __restrict__ idx, const float* __restrict__ embed,
                         const float* __restrict__ w, const float* __restrict__ bb,
                         float* __restrict__ out) {
  size_t row = blockIdx.x;
  const float* x = embed + (size_t)idx[row] * kD;
  float mean, rstd;
  ln_stats(x, mean, rstd);
  float* o = out + row * kD;
  for (int i = threadIdx.x; i < kD; i += 256)
    o[i] = (x[i] - mean) * rstd * w[i] + bb[i];
}

// ---------------- TimeMix decay scan + GN partials (fused) -----------------
#define TMCH 32
#define DGRP 8
__global__ void timemix2(const float* __restrict__ rkv, const float* __restrict__ decay_l,
                         float* __restrict__ out) {
  int b = blockIdx.x / (kD / DGRP);
  int dg = blockIdx.x % (kD / DGRP);
  int d = dg * DGRP + threadIdx.x;
  int chunk = threadIdx.y;
  const int clen = kT / TMCH;  // 32
  int t0 = chunk * clen;

  float dec = 1.f / (1.f + expf(-decay_l[d]));
  float logdec = logf(fmaxf(dec, 1e-7f));
  size_t base = (size_t)b * kT * 3 * kD;
  const float* rp = rkv + base + d;
  const float* kp = rkv + base + kD + d;
  const float* vp = rkv + base + 2 * kD + d;
  float* op = out + (size_t)b * kT * kD + d;

  // pass 1: compute kv/denom, cache in registers
  float kvd[32];
  float s = 0.f;
#pragma unroll
  for (int q = 0; q < 32; q++) {
    int t = t0 + q;
    float scale = __expf((float)t * logdec);
    float denom = fmaxf(scale, 1e-10f);
    kvd[q] = __fdividef(kp[(size_t)t * 3 * kD] * vp[(size_t)t * 3 * kD], denom);
    s += kvd[q];
  }
  __shared__ float cs[TMCH][DGRP];
  cs[chunk][threadIdx.x] = s;
  __syncthreads();
  float cum = 0.f;
  for (int c = 0; c < chunk; c++) cum += cs[c][threadIdx.x];

  // pass 2: write outputs, accumulate GN partials
  double ps = 0.0, pss = 0.0;
#pragma unroll
  for (int q = 0; q < 32; q++) {
    int t = t0 + q;
    float scale = __expf((float)t * logdec);
    cum += kvd[q];
    float y = rp[(size_t)t * 3 * kD] * (cum * scale);
    op[(size_t)t * kD] = y;
    ps += (double)y;
    pss += (double)y * (double)y;
  }

  // block-reduce partials (256 threads) -> g_gn_part[b][dg]
  __shared__ double sh1[32], sh2[32];
  int tid = threadIdx.y * DGRP + threadIdx.x;
  for (int off = 16; off; off >>= 1) {
    ps += __shfl_down_sync(0xffffffffu, ps, off);
    pss += __shfl_down_sync(0xffffffffu, pss, off);
  }
  if ((tid & 31) == 0) { sh1[tid >> 5] = ps; sh2[tid >> 5] = pss; }
  __syncthreads();
  if (tid < 32) {
    ps = tid < 8 ? sh1[tid] : 0.0;
    pss = tid < 8 ? sh2[tid] : 0.0;
    for (int off = 4; off; off >>= 1) {
      ps += __shfl_down_sync(0xffffffffu, ps, off);
      pss += __shfl_down_sync(0xffffffffu, pss, off);
    }
    if (tid == 0) { g_gn_part[b][dg][0] = ps; g_gn_part[b][dg][1] = pss; }
  }
}

// GN apply -> fp16 single A-layout (for Wotm GEMM)
__global__ void gn_apply1h(const float* __restrict__ in, const float* __restrict__ gw,
                           const float* __restrict__ gb, __half* __restrict__ out1) {
  int b = blockIdx.y;
  __shared__ float sh_m, sh_r;
  if (threadIdx.x == 0) {
    double s = 0.0, ss = 0.0;
    for (int c2 = 0; c2 < 128; c2++) { s += g_gn_part[b][c2][0]; ss += g_gn_part[b][c2][1]; }
    double inv = 1.0 / (double)(kT * kD);
    double m = s * inv;
    double var = ss * inv - m * m;
    sh_m = (float)m;
    sh_r = rsqrtf((float)var + 1e-5f);
  }
  __syncthreads();
  int idx = blockIdx.x * blockDim.x + threadIdx.x;
  int d = idx & (kD - 1);
  size_t row = (size_t)b * kT + (idx >> 10);
  float y = (in[(size_t)b * kT * kD + idx] - sh_m) * sh_r * gw[d] + gb[d];
  out1[row * kD + d] = __float2half_rn(y);
}

// ---------------- per-row logit stats (single-pass online softmax) ----------
// HALF=0: fp32 logits. HALF=1: fp16 logits.
template <int HALF>
__global__ void rowstats(const void* __restrict__ logits, const int* __restrict__ targets,
                         float* __restrict__ lse, float* __restrict__ tgt,
                         int* __restrict__ amax, float* __restrict__ ent) {
  int row = blockIdx.x;
  int tid = threadIdx.x;
  const float* Lf = (const float*)logits + (size_t)row * kV;
  const __half* Lh = (const __half*)logits + (size_t)row * kV;

  float M = -3.4e38f, S = 0.f, T2 = 0.f;
  int mi = 0;
  for (int i = tid; i < kV; i += 256) {
    float v = HALF ? __half2float(Lh[i]) : Lf[i];
    if (v > M) {
      float f = __expf(M - v);
      T2 = (T2 + S * (M - v)) * f;
      S = S * f;
      M = v; mi = i;
      S += 1.f;
    } else {
      float e = __expf(v - M);
      S += e;
      T2 += e * (v - M);
    }
  }
  __shared__ float sM[256], sS[256], sT[256];
  __shared__ int sI[256];
  sM[tid] = M; sS[tid] = S; sT[tid] = T2; sI[tid] = mi;
  __syncthreads();
  for (int off = 128; off > 0; off >>= 1) {
    if (tid < off) {
      float Ma = sM[tid], Sa = sS[tid], Ta = sT[tid];
      float Mb = sM[tid + off], Sb = sS[tid + off], Tb = sT[tid + off];
      int ia = sI[tid], ib = sI[tid + off];
      float Mx = fmaxf(Ma, Mb);
      float fa = __expf(Ma - Mx), fb = __expf(Mb - Mx);
      sS[tid] = Sa * fa + Sb * fb;
      sT[tid] = (Ta + Sa * (Ma - Mx)) * fa + (Tb + Sb * (Mb - Mx)) * fb;
      sM[tid] = Mx;
      sI[tid] = (Mb > Ma || (Mb == Ma && ib < ia)) ? ib : ia;
    }
    __syncthreads();
  }
  if (tid == 0) {
    float Sf = sS[0];
    lse[row] = sM[0] + logf(Sf);
    if (ent) ent[row] = logf(Sf) - sT[0] / Sf;
    amax[row] = sI[0];
    int tg = targets[row];
    tgt[row] = HALF ? __half2float(Lh[tg]) : Lf[tg];
  }
}

// ---------------- exit gate ----------------
__global__ void colmean1h(const __half* __restrict__ he1, float* __restrict__ hbar) {
  int d = blockIdx.x * blockDim.x + threadIdx.x;
  int b = blockIdx.y;
  float s = 0.f;
  const __half* p = he1 + (size_t)b * kT * kD;
  for (int t = 0; t < kT; t++) s += __half2float(p[(size_t)t * kD + d]);
  hbar[b * kD + d] = s / (float)kT;
}

__global__ void gate_kernel(const float* __restrict__ hbar, const float* __restrict__ w1,
                            const float* __restrict__ b1, const float* __restrict__ w2,
                            const float* __restrict__ b2, int j) {
  __shared__ float g[kB][64];
  int tid = threadIdx.x;
  if (tid < kB * 64) {
    int b = tid / 64, u = tid % 64;
    float s = 0.f;
    const float* hp = hbar + b * kD;
    const float* wp = w1 + (size_t)u * kD;
    for (int d = 0; d < kD; d++) s += hp[d] * wp[d];
    g[b][u] = fmaxf(s + b1[u], 0.f);
  }
  __syncthreads();
  if (tid < kB) {
    float s = 0.f;
    for (int u = 0; u < 64; u++) s += g[tid][u] * w2[u];
    g_conf[j * kB + tid] = 1.f / (1.f + expf(-(s + b2[0])));
  }
}

// ---------------- loss assembly ----------------
__global__ void loss_kernel(float* __restrict__ loss_out) {
  int tid = threadIdx.x;
  float ce_f = 0.f, ce_e[2] = {0.f, 0.f};
  float ag[2][2] = {{0.f, 0.f}, {0.f, 0.f}};
  float oc[2] = {0.f, 0.f};
  const float maxent = logf((float)kV);
  for (int r = tid; r < kN; r += 256) {
    int fp = g_amax_f[r];
    ce_f += g_lse_f[r] - g_tgt_f[r];
    int b = r / kT;
#pragma unroll
    for (int j = 0; j < 2; j++) {
      ce_e[j] += g_lse_e[j * kN + r] - g_tgt_e[j * kN + r];
      int ep = g_amax_e[j * kN + r];
      if (ep == fp) ag[j][b] += 1.f;
      else oc[j] += (1.f - g_ent_e[j * kN + r] / maxent);
    }
  }
  __shared__ float sh[256];
  float vals[9] = {ce_f, ce_e[0], ce_e[1], ag[0][0], ag[0][1], ag[1][0], ag[1][1], oc[0], oc[1]};
  float red[9];
#pragma unroll
  for (int q = 0; q < 9; q++) {
    sh[tid] = vals[q];
    __syncthreads();
    for (int off = 128; off > 0; off >>= 1) { if (tid < off) sh[tid] += sh[tid + off]; __syncthreads(); }
    red[q] = sh[0];
    __syncthreads();
  }
  if (tid == 0) {
    const float w[2] = {0.3f, 0.5f};
    float loss = red[0] / (float)kN;
    for (int j = 0; j < 2; j++) {
      loss += w[j] * (red[1 + j] / (float)kN);
      float bce = 0.f;
      for (int b = 0; b < kB; b++) {
        float agree = red[3 + j * 2 + b] / (float)kT;
        float c = fminf(fmaxf(g_conf[j * kB + b], 1e-7f), 1.f - 1e-7f);
        bce += -(agree * logf(c) + (1.f - agree) * logf(1.f - c));
      }
      loss += 0.5f * (bce / (float)kB);
      loss += 0.1f * (red[7 + j] / (float)kN);
    }
    loss_out[0] = loss;
  }
}

// ---------------- host orchestration ----------------
#define DSMEM (NST * STAGE_B)  // 61440

extern "C" void kernel_launch(void* const* d_in, const int* in_sizes, int n_in,
                              void* d_out, int out_size) {
  const int* idx = (const int*)d_in[0];
  const int* targets = (const int*)d_in[1];
  const float* embed = (const float*)d_in[2];
  const float* ln_in_w = (const float*)d_in[3];
  const float* ln_in_b = (const float*)d_in[4];
  const float* Wr = (const float*)d_in[5];
  const float* Wk = (const float*)d_in[6];
  const float* Wv = (const float*)d_in[7];
  const float* Wo_tm = (const float*)d_in[8];
  const float* decay = (const float*)d_in[9];
  const float* gn_w = (const float*)d_in[10];
  const float* gn_b = (const float*)d_in[11];
  const float* ln1_w = (const float*)d_in[12];
  const float* ln1_b = (const float*)d_in[13];
  const float* ln2_w = (const float*)d_in[14];
  const float* ln2_b = (const float*)d_in[15];
  const float* W1 = (const float*)d_in[16];
  const float* W2 = (const float*)d_in[17];
  const float* Wo_cm = (const float*)d_in[18];
  const float* ln_out_w = (const float*)d_in[19];
  const float* ln_out_b = (const float*)d_in[20];
  const float* exit_ln_w = (const float*)d_in[21];
  const float* exit_ln_b = (const float*)d_in[22];
  const float* exit_head = (const float*)d_in[23];
  const float* gate_w1 = (const float*)d_in[24];
  const float* gate_b1 = (const float*)d_in[25];
  const float* gate_w2 = (const float*)d_in[26];
  const float* gate_b2 = (const float*)d_in[27];
  float* out = (float*)d_out;

  float *xp, *rkvp, *attp, *elp, *hbarp;
  float *lse_f, *tgt_f, *lse_e, *tgt_e, *ent_e;
  int *amax_f, *amax_e;
  __half *h1p, *ff2hp, *Wrkvh, *Wotmh, *W123h, *Wocmh, *embedh, *exith;
  cudaGetSymbolAddress((void**)&xp, g_x);
  cudaGetSymbolAddress((void**)&rkvp, g_rkv);
  cudaGetSymbolAddress((void**)&attp, g_att);
  cudaGetSymbolAddress((void**)&elp, g_elog);
  cudaGetSymbolAddress((void**)&hbarp, g_hbar);
  cudaGetSymbolAddress((void**)&lse_f, g_lse_f);
  cudaGetSymbolAddress((void**)&tgt_f, g_tgt_f);
  cudaGetSymbolAddress((void**)&amax_f, g_amax_f);
  cudaGetSymbolAddress((void**)&lse_e, g_lse_e);
  cudaGetSymbolAddress((void**)&tgt_e, g_tgt_e);
  cudaGetSymbolAddress((void**)&ent_e, g_ent_e);
  cudaGetSymbolAddress((void**)&amax_e, g_amax_e);
  cudaGetSymbolAddress((void**)&h1p, g_h1);
  cudaGetSymbolAddress((void**)&ff2hp, g_ff2h);
  cudaGetSymbolAddress((void**)&Wrkvh, g_Wrkvh);
  cudaGetSymbolAddress((void**)&Wotmh, g_Wotmh);
  cudaGetSymbolAddress((void**)&W123h, g_W123h);
  cudaGetSymbolAddress((void**)&Wocmh, g_Wocmh);
  cudaGetSymbolAddress((void**)&embedh, g_embedh);
  cudaGetSymbolAddress((void**)&exith, g_exith);

  cudaFuncSetAttribute((const void*)gemm3<0>, cudaFuncAttributeMaxDynamicSharedMemorySize, DSMEM);
  cudaFuncSetAttribute((const void*)gemm3<1>, cudaFuncAttributeMaxDynamicSharedMemorySize, DSMEM);
  cudaFuncSetAttribute((const void*)gemm3<2>, cudaFuncAttributeMaxDynamicSharedMemorySize, DSMEM);
  cudaFuncSetAttribute((const void*)gemm3<3>, cudaFuncAttributeMaxDynamicSharedMemorySize, DSMEM);
  cudaFuncSetAttribute((const void*)gemm3<4>, cudaFuncAttributeMaxDynamicSharedMemorySize, DSMEM);

  dim3 g_rkvg(kN / BM, (3 * kD) / BN);   // (16,24)
  dim3 g_dd(kN / BM, kD / BN);           // (16,8)
  dim3 g_w12(kN / BM, (2 * kDFF) / BN);  // (16,64) over interleaved cols
  dim3 g_vg(kN / BM, kV / BN);           // (16,250)

  const long L4 = 0x7fffffffffffffffL;

  // ---- launch #1: fp16 TimeMix weight conversion (single-term) ----
  {
    ConvArgs a1;
    long t = (long)kL * kD * kD / 4;
    a1.s[0] = {Wr, Wrkvh, kD, kD, 3 * kD, 0, 2, 1, t};
    a1.s[1] = {Wk, Wrkvh, kD, kD, 3 * kD, kD, 2, 1, 2 * t};
    a1.s[2] = {Wv, Wrkvh, kD, kD, 3 * kD, 2 * kD, 2, 1, 3 * t};
    a1.s[3] = {Wo_tm, Wotmh, kD, kL * kD, kL * kD, 0, 2, 1, 4 * t};
    conv_multi<<<(unsigned)((4 * t + 255) / 256), 256>>>(a1, 4 * t);
  }

  // ---- launches #2-#4: embed_ln, ln1(l0), rkv GEMM(l0)  [#4 = ncu target] --
  embed_ln<<<kN, 256>>>(idx, embed, ln_in_w, ln_in_b, xp);
  ln_rows1h<<<kN, 256>>>(xp, h1p, ln1_w, ln1_b);
  gemm3<1><<<g_rkvg, 256, DSMEM>>>(h1p, Wrkvh, rkvp, 3 * kD, kD, kD);

  // ---- remaining weight conversions ----
  {
    ConvArgs a2;  // fp16 single ChannelMix weights (W1/W2 row-interleaved)
    long u = (long)kL * kDFF * kD / 4;
    a2.s[0] = {W1, W123h, kD, kDFF, 2 * kDFF, 0, 2, 2, u};
    a2.s[1] = {W2, W123h, kD, kDFF, 2 * kDFF, 1, 2, 2, 2 * u};
    a2.s[2] = {Wo_cm, Wocmh, kDFF, kL * kD, kL * kD, 0, 2, 1, 3 * u};
    a2.s[3] = {nullptr, nullptr, 4, 1, 1, 0, 2, 1, L4};
    conv_multi<<<(unsigned)((3 * u + 255) / 256), 256>>>(a2, 3 * u);
    ConvArgs a3;  // fp16 single vocab weights
    long e1 = (long)kV * kD / 4, e2 = 2L * kV * kD / 4;
    a3.s[0] = {embed, embedh, kD, kV, kV, 0, 2, 1, e1};
    a3.s[1] = {exit_head, exith, kD, 2 * kV, 2 * kV, 0, 2, 1, e1 + e2};
    a3.s[2] = {nullptr, nullptr, 4, 1, 1, 0, 2, 1, L4};
    a3.s[3] = {nullptr, nullptr, 4, 1, 1, 0, 2, 1, L4};
    conv_multi<<<(unsigned)((e1 + e2 + 255) / 256), 256>>>(a3, e1 + e2);
  }

  for (int i = 0; i < kL; i++) {
    // --- TimeMix (layer 0's ln1+rkv already launched above) ---
    if (i > 0) {
      ln_rows1h<<<kN, 256>>>(xp, h1p, ln1_w + i * kD, ln1_b + i * kD);
      gemm3<1><<<g_rkvg, 256, DSMEM>>>(h1p, Wrkvh + (size_t)i * 3 * kD * kD, rkvp,
                                       3 * kD, kD, kD);
    }
    timemix2<<<kB * (kD / DGRP), dim3(DGRP, TMCH)>>>(rkvp, decay + i * kD, attp);
    gn_apply1h<<<dim3(kT * kD / 256, kB), 256>>>(attp, gn_w + i * kD, gn_b + i * kD, h1p);
    gemm3<2><<<g_dd, 256, DSMEM>>>(h1p, Wotmh + (size_t)i * kD * kD, xp, kD, kD, 0);
    // --- ChannelMix (single-term fp16, fused SwiGLU epilogue) ---
    ln_rows1h<<<kN, 256>>>(xp, h1p, ln2_w + i * kD, ln2_b + i * kD);
    gemm3<3><<<g_w12, 256, DSMEM>>>(h1p, W123h + (size_t)i * 2 * kDFF * kD,
                                    (float*)ff2hp, kDFF, kD, 0);
    gemm3<2><<<g_dd, 256, DSMEM>>>(ff2hp, Wocmh + (size_t)i * kD * kDFF,
                                   xp, kD, kDFF, 0);
    // --- early exits (fp16 logits + single-pass stats) ---
    if (i == 3 || i == 7) {
      int j = (i == 3) ? 0 : 1;
      ln_rows1h<<<kN, 256>>>(xp, h1p, exit_ln_w + j * kD, exit_ln_b + j * kD);
      gemm3<4><<<g_vg, 256, DSMEM>>>(h1p, exith + (size_t)j * kV * kD, elp, kV, kD, 0);
      rowstats<1><<<kN, 256>>>(elp, targets, lse_e + j * kN, tgt_e + j * kN,
                               amax_e + j * kN, ent_e + j * kN);
      colmean1h<<<dim3(kD / 256, kB), 256>>>(h1p, hbarp);
      gate_kernel<<<1, 128>>>(hbarp, gate_w1 + (size_t)j * 64 * kD, gate_b1 + j * 64,
                              gate_w2 + j * 64, gate_b2 + j, j);
    }
  }

  // final LN + tied head (fp32 logits into d_out, single-pass stats)
  ln_rows1h<<<kN, 256>>>(xp, h1p, ln_out_w, ln_out_b);
  gemm3<0><<<g_vg, 256, DSMEM>>>(h1p, embedh, out, kV, kD, 0);
  rowstats<0><<<kN, 256>>>(out, targets, lse_f, tgt_f, amax_f, (float*)nullptr);
  loss_kernel<<<1, 256>>>(out + (size_t)kN * kV);
}

// round 15
// speedup vs baseline: 1.1320x; 1.1320x over previous
#include <cuda_runtime.h>
#include <cuda_bf16.h>
#include <cuda_fp16.h>
#include <math.h>
#include <stdint.h>

// ---------------- constants ----------------
#define kB 2
#define kT 1024
#define kD 1024
#define kDFF 4096
#define kV 32000
#define kL 12
#define kN (kB * kT)  // 2048 rows

typedef __nv_bfloat16 bf16;

// ---------------- scratch ----------------
__device__ float g_x[kN * kD];
__device__ float g_rkv[kN * 3 * kD];
__device__ float g_att[kN * kD];
__device__ float g_elog[(size_t)kN * kV];     // exit logits (fp16, aliased)
__device__ __half g_h1[kN * kD];              // fp16 single A (all GEMM inputs)
__device__ __half g_ff2h[(size_t)kN * kDFF];  // fp16 single A for Wocm (silu output)
// weights: ALL single-term fp16 K'=K. W12 rows interleaved W1/W2.
__device__ __half g_Wrkvh[(size_t)kL * 3 * kD * kD];
__device__ __half g_Wotmh[(size_t)kL * kD * kD];
__device__ __half g_W123h[(size_t)kL * 2 * kDFF * kD];
__device__ __half g_Wocmh[(size_t)kL * kD * kDFF];
__device__ __half g_embedh[(size_t)kV * kD];
__device__ __half g_exith[(size_t)2 * kV * kD];

__device__ double g_gn_part[kB][64][2];
__device__ float g_hbar[kB * kD];
__device__ float g_conf[2 * kB];
__device__ float g_lse_f[kN], g_tgt_f[kN];
__device__ int   g_amax_f[kN];
__device__ float g_lse_e[2 * kN], g_tgt_e[2 * kN], g_ent_e[2 * kN];
__device__ int   g_amax_e[2 * kN];

// ---------------- helpers ----------------
__device__ __forceinline__ uint32_t smem_u32(const void* p) {
  return (uint32_t)__cvta_generic_to_shared(p);
}
__device__ __forceinline__ void cp16(uint32_t s, const void* g) {
  asm volatile("cp.async.ca.shared.global [%0], [%1], 16;\n" ::"r"(s), "l"(g));
}
__device__ __forceinline__ void cp_commit() { asm volatile("cp.async.commit_group;\n"); }
template <int NW>
__device__ __forceinline__ void cp_wait() { asm volatile("cp.async.wait_group %0;\n" ::"n"(NW)); }
__device__ __forceinline__ void ldm_x4(uint32_t* r, uint32_t a) {
  asm volatile("ldmatrix.sync.aligned.m8n8.x4.shared.b16 {%0,%1,%2,%3}, [%4];\n"
               : "=r"(r[0]), "=r"(r[1]), "=r"(r[2]), "=r"(r[3]) : "r"(a));
}
__device__ __forceinline__ void mma_f16(float* d, const uint32_t* a, const uint32_t* b) {
  asm volatile(
      "mma.sync.aligned.m16n8k16.row.col.f32.f16.f16.f32 "
      "{%0,%1,%2,%3}, {%4,%5,%6,%7}, {%8,%9}, {%0,%1,%2,%3};\n"
      : "+f"(d[0]), "+f"(d[1]), "+f"(d[2]), "+f"(d[3])
      : "r"(a[0]), "r"(a[1]), "r"(a[2]), "r"(a[3]), "r"(b[0]), "r"(b[1]));
}

// ---------------- segmented weight conversion ----------------
struct ConvSeg {
  const float* in;
  void* out;
  int K;
  int srcRPL;
  int outRPL;
  int outOff;
  int fmt;      // 2 = single-term fp16
  int rstride;  // output row spacing (2 = interleave)
  long cum;     // cumulative END (in float4 units)
};
struct ConvArgs { ConvSeg s[4]; };

__global__ void conv_multi(ConvArgs a, long grand) {
  long i = (long)blockIdx.x * blockDim.x + threadIdx.x;
  if (i >= grand) return;
  int si = 0;
  while (i >= a.s[si].cum) si++;
  long local = i - (si ? a.s[si - 1].cum : 0L);
  const ConvSeg g = a.s[si];
  int K4 = g.K >> 2;
  long rs = local / K4;
  int c = (int)(local % K4) << 2;
  long layer = rs / g.srcRPL;
  int r = (int)(rs % g.srcRPL);
  long orow = layer * g.outRPL + g.outOff + (long)r * g.rstride;
  float4 v = ((const float4*)g.in)[local];
  float vv[4] = {v.x, v.y, v.z, v.w};
  ushort h[4];
#pragma unroll
  for (int e = 0; e < 4; e++) h[e] = __half_as_ushort(__float2half_rn(vv[e]));
  uint2 hp = {(uint32_t)h[0] | ((uint32_t)h[1] << 16), (uint32_t)h[2] | ((uint32_t)h[3] << 16)};
  __half* ob = (__half*)g.out + orow * (long)g.K;
  *(uint2*)(ob + c) = hp;
}

// ---------------- pipelined fp16 tensor-core GEMM ----------------
// C[n,m] = sum_k A[n,k]*W[m,k], fp16 operands, fp32 accum.
// MODE 0: store fp32. 1: sigmoid where col<sigcut else store (fp32).
// MODE 2: += C (fp32). MODE 3: fused SwiGLU -> fp16 at col gc/2 (M=kDFF).
// MODE 4: store fp16.
#define BM 128
#define BN 128
#define BK 32
#define NST 3
#define LDSB 80  // bytes per smem row (40 elems)
#define STAGE_B ((BM + BN) * LDSB)  // 20480

template <int MODE>
__global__ void __launch_bounds__(256, 2)
gemm3(const __half* __restrict__ A, const __half* __restrict__ W,
      float* __restrict__ C, int M, int Kp, int sigcut) {
  extern __shared__ bf16 dynsmem[];
  uint32_t sbase = smem_u32(dynsmem);

  int tid = threadIdx.x;
  int lane = tid & 31, wid = tid >> 5;
  int wm = wid >> 2, wn = wid & 3;  // 2x4 warps, warp tile 64x32

  const __half* Ab = A + (size_t)(blockIdx.x * BM) * Kp;
  const __half* Wb = W + (size_t)(blockIdx.y * BN) * Kp;

  int r0 = tid >> 2, c0 = (tid & 3);
  int r1 = (tid + 256) >> 2, c1 = (tid & 3);

  float acc[4][4][4];
#pragma unroll
  for (int i = 0; i < 4; i++)
#pragma unroll
    for (int j = 0; j < 4; j++)
#pragma unroll
      for (int q = 0; q < 4; q++) acc[i][j][q] = 0.f;

  int KT = Kp / BK;

  int laneA = (wm * 64 + (lane & 7) + ((lane >> 3) & 1) * 8) * LDSB + ((lane >> 4)) * 16;
  int laneW = BM * LDSB + (wn * 32 + (lane & 7) + (lane >> 4) * 8) * LDSB +
              (((lane >> 3) & 1)) * 16;

#define ISSUE(stage, kt)                                                            \
  {                                                                                 \
    uint32_t sb = sbase + (uint32_t)(stage) * STAGE_B;                              \
    const __half* ga = Ab + (size_t)(kt) * BK;                                      \
    const __half* gw = Wb + (size_t)(kt) * BK;                                      \
    cp16(sb + r0 * LDSB + c0 * 16, ga + (size_t)r0 * Kp + c0 * 8);                  \
    cp16(sb + r1 * LDSB + c1 * 16, ga + (size_t)r1 * Kp + c1 * 8);                  \
    cp16(sb + BM * LDSB + r0 * LDSB + c0 * 16, gw + (size_t)r0 * Kp + c0 * 8);      \
    cp16(sb + BM * LDSB + r1 * LDSB + c1 * 16, gw + (size_t)r1 * Kp + c1 * 8);      \
  }

  ISSUE(0, 0); cp_commit();
  ISSUE(1, 1); cp_commit();

  for (int kt = 0; kt < KT; kt++) {
    cp_wait<1>();
    __syncthreads();
    int st = kt % NST;
    if (kt + 2 < KT) { ISSUE((kt + 2) % NST, kt + 2); }
    cp_commit();

    uint32_t stA = sbase + st * STAGE_B + laneA;
    uint32_t stW = sbase + st * STAGE_B + laneW;
#pragma unroll
    for (int kk = 0; kk < 2; kk++) {
      uint32_t b[8];
      ldm_x4(b, stW + kk * 32);
      ldm_x4(b + 4, stW + 16 * LDSB + kk * 32);
#pragma unroll
      for (int mt = 0; mt < 4; mt++) {
        uint32_t a[4];
        ldm_x4(a, stA + mt * 16 * LDSB + kk * 32);
#pragma unroll
        for (int nt = 0; nt < 4; nt++) mma_f16(acc[mt][nt], a, b + nt * 2);
      }
    }
  }
#undef ISSUE

  // epilogue
#pragma unroll
  for (int mt = 0; mt < 4; mt++) {
#pragma unroll
    for (int nt = 0; nt < 4; nt++) {
      int gr0 = blockIdx.x * BM + wm * 64 + mt * 16 + (lane >> 2);
      int gc = blockIdx.y * BN + wn * 32 + nt * 8 + ((lane & 3) << 1);
#pragma unroll
      for (int half = 0; half < 2; half++) {
        int gr = gr0 + half * 8;
        float v0 = acc[mt][nt][half * 2 + 0];
        float v1 = acc[mt][nt][half * 2 + 1];
        if (MODE == 3) {
          float y = (v0 / (1.f + expf(-v0))) * v1;
          __half* oh = (__half*)C;
          oh[(size_t)gr * M + (gc >> 1)] = __float2half_rn(y);
        } else if (MODE == 4) {
          __half* oh = (__half*)C;
          size_t off = (size_t)gr * M + gc;
          __half2 o2h = {__float2half_rn(v0), __float2half_rn(v1)};
          *(__half2*)&oh[off] = o2h;
        } else {
          size_t off = (size_t)gr * M + gc;
          if (MODE == 1) {
            if (gc < sigcut) {
              v0 = 1.f / (1.f + expf(-v0));
              v1 = 1.f / (1.f + expf(-v1));
            }
          } else if (MODE == 2) {
            float2 old = *(const float2*)&C[off];
            v0 += old.x; v1 += old.y;
          }
          float2 o2 = {v0, v1};
          *(float2*)&C[off] = o2;
        }
      }
    }
  }
}

// ---------------- LayerNorm ----------------
__device__ __forceinline__ void ln_stats(const float* __restrict__ x, float& mean,
                                         float& rstd) {
  int tid = threadIdx.x;
  float s = 0.f, ss = 0.f;
  for (int i = tid; i < kD; i += 256) { float v = x[i]; s += v; ss += v * v; }
  __shared__ float shs[32], shss[32];
  for (int off = 16; off; off >>= 1) {
    s += __shfl_down_sync(0xffffffffu, s, off);
    ss += __shfl_down_sync(0xffffffffu, ss, off);
  }
  if ((tid & 31) == 0) { shs[tid >> 5] = s; shss[tid >> 5] = ss; }
  __syncthreads();
  if (tid < 32) {
    s = tid < 8 ? shs[tid] : 0.f;
    ss = tid < 8 ? shss[tid] : 0.f;
    for (int off = 4; off; off >>= 1) {
      s += __shfl_down_sync(0xffffffffu, s, off);
      ss += __shfl_down_sync(0xffffffffu, ss, off);
    }
    if (tid == 0) { shs[0] = s; shss[0] = ss; }
  }
  __syncthreads();
  mean = shs[0] / (float)kD;
  float var = shss[0] / (float)kD - mean * mean;
  rstd = rsqrtf(var + 1e-5f);
}

__global__ void ln_rows1h(const float* __restrict__ in, __half* __restrict__ out1,
                          const float* __restrict__ w, const float* __restrict__ bb) {
  size_t row = blockIdx.x;
  const float* x = in + row * kD;
  float mean, rstd;
  ln_stats(x, mean, rstd);
  __half* ob = out1 + row * kD;
  for (int i = threadIdx.x; i < kD; i += 256) {
    float y = (x[i] - mean) * rstd * w[i] + bb[i];
    ob[i] = __float2half_rn(y);
  }
}

__global__ void embed_ln(const int* __restrict__ idx, const float* __restrict__ embed,
                         const float* __restrict__ w, const float* __restrict__ bb,
                         float* __restrict__ out) {
  size_t row = blockIdx.x;
  const float* x = embed + (size_t)idx[row] * kD;
  float mean, rstd;
  ln_stats(x, mean, rstd);
  float* o = out + row * kD;
  for (int i = threadIdx.x; i < kD; i += 256)
    o[i] = (x[i] - mean) * rstd * w[i] + bb[i];
}

// ---------------- TimeMix decay scan (R13-proven) ----------------
#define TMCH 32
#define DGRP 8
__global__ void timemix2(const float* __restrict__ rkv, const float* __restrict__ decay_l,
                         float* __restrict__ out) {
  int b = blockIdx.x / (kD / DGRP);
  int dg = blockIdx.x % (kD / DGRP);
  int d = dg * DGRP + threadIdx.x;
  int chunk = threadIdx.y;
  const int clen = kT / TMCH;
  int t0 = chunk * clen;

  float dec = 1.f / (1.f + expf(-decay_l[d]));
  float logdec = logf(fmaxf(dec, 1e-7f));
  size_t base = (size_t)b * kT * 3 * kD;
  const float* rp = rkv + base + d;
  const float* kp = rkv + base + kD + d;
  const float* vp = rkv + base + 2 * kD + d;
  float* op = out + (size_t)b * kT * kD + d;

  float s = 0.f;
  for (int t = t0; t < t0 + clen; t++) {
    float scale = __expf((float)t * logdec);
    float denom = fmaxf(scale, 1e-10f);
    s += __fdividef(kp[(size_t)t * 3 * kD] * vp[(size_t)t * 3 * kD], denom);
  }
  __shared__ float cs[TMCH][DGRP];
  cs[chunk][threadIdx.x] = s;
  __syncthreads();
  float cum = 0.f;
  for (int c = 0; c < chunk; c++) cum += cs[c][threadIdx.x];
  for (int t = t0; t < t0 + clen; t++) {
    float scale = __expf((float)t * logdec);
    float denom = fmaxf(scale, 1e-10f);
    cum += __fdividef(kp[(size_t)t * 3 * kD] * vp[(size_t)t * 3 * kD], denom);
    op[(size_t)t * kD] = rp[(size_t)t * 3 * kD] * (cum * scale);
  }
}

// ---------------- GroupNorm(1,D) over (T,D) per batch (partials) -----------
__global__ void gn_reduce(const float* __restrict__ in) {
  const int CH = 64;
  int b = blockIdx.x / CH, chunk = blockIdx.x % CH;
  const int n = kT * kD / CH;
  const float* p = in + (size_t)b * kT * kD + (size_t)chunk * n;
  double s = 0.0, ss = 0.0;
  for (int i = threadIdx.x; i < n; i += blockDim.x) {
    double v = (double)p[i];
    s += v; ss += v * v;
  }
  __shared__ double sh1[32], sh2[32];
  for (int off = 16; off; off >>= 1) {
    s += __shfl_down_sync(0xffffffffu, s, off);
    ss += __shfl_down_sync(0xffffffffu, ss, off);
  }
  int tid = threadIdx.x;
  if ((tid & 31) == 0) { sh1[tid >> 5] = s; sh2[tid >> 5] = ss; }
  __syncthreads();
  int nw = (blockDim.x + 31) >> 5;
  if (tid < 32) {
    s = tid < nw ? sh1[tid] : 0.0;
    ss = tid < nw ? sh2[tid] : 0.0;
    for (int off = 16; off; off >>= 1) {
      s += __shfl_down_sync(0xffffffffu, s, off);
      ss += __shfl_down_sync(0xffffffffu, ss, off);
    }
    if (tid == 0) { g_gn_part[b][chunk][0] = s; g_gn_part[b][chunk][1] = ss; }
  }
}

// GN apply -> fp16 single A-layout (for Wotm GEMM)
__global__ void gn_apply1h(const float* __restrict__ in, const float* __restrict__ gw,
                           const float* __restrict__ gb, __half* __restrict__ out1) {
  int b = blockIdx.y;
  __shared__ float sh_m, sh_r;
  if (threadIdx.x == 0) {
    double s = 0.0, ss = 0.0;
    for (int c2 = 0; c2 < 64; c2++) { s += g_gn_part[b][c2][0]; ss += g_gn_part[b][c2][1]; }
    double inv = 1.0 / (double)(kT * kD);
    double m = s * inv;
    double var = ss * inv - m * m;
    sh_m = (float)m;
    sh_r = rsqrtf((float)var + 1e-5f);
  }
  __syncthreads();
  int idx = blockIdx.x * blockDim.x + threadIdx.x;
  int d = idx & (kD - 1);
  size_t row = (size_t)b * kT + (idx >> 10);
  float y = (in[(size_t)b * kT * kD + idx] - sh_m) * sh_r * gw[d] + gb[d];
  out1[row * kD + d] = __float2half_rn(y);
}

// ---------------- per-row logit stats (two-pass, R13 algorithm) -------------
// HALF=0: fp32 logits. HALF=1: fp16 logits.
template <int HALF>
__global__ void rowstats(const void* __restrict__ logits, const int* __restrict__ targets,
                         float* __restrict__ lse, float* __restrict__ tgt,
                         int* __restrict__ amax, float* __restrict__ ent) {
  int row = blockIdx.x;
  int tid = threadIdx.x;
  const float* Lf = (const float*)logits + (size_t)row * kV;
  const __half* Lh = (const __half*)logits + (size_t)row * kV;

  __shared__ float svals[256];
  __shared__ int sidx[256];
  float m = -3.4e38f; int mi = 0;
  for (int i = tid; i < kV; i += 256) {
    float v = HALF ? __half2float(Lh[i]) : Lf[i];
    if (v > m) { m = v; mi = i; }
  }
  svals[tid] = m; sidx[tid] = mi;
  __syncthreads();
  for (int off = 128; off > 0; off >>= 1) {
    if (tid < off) {
      float v2 = svals[tid + off]; int i2 = sidx[tid + off];
      if (v2 > svals[tid] || (v2 == svals[tid] && i2 < sidx[tid])) { svals[tid] = v2; sidx[tid] = i2; }
    }
    __syncthreads();
  }
  float M = svals[0]; int MI = sidx[0];
  __syncthreads();
  float s = 0.f, t2 = 0.f;
  for (int i = tid; i < kV; i += 256) {
    float v = (HALF ? __half2float(Lh[i]) : Lf[i]) - M;
    float e = __expf(v);
    s += e; t2 += e * v;
  }
  svals[tid] = s; __syncthreads();
  for (int off = 128; off > 0; off >>= 1) { if (tid < off) svals[tid] += svals[tid + off]; __syncthreads(); }
  float S = svals[0]; __syncthreads();
  svals[tid] = t2; __syncthreads();
  for (int off = 128; off > 0; off >>= 1) { if (tid < off) svals[tid] += svals[tid + off]; __syncthreads(); }
  float T2 = svals[0];
  if (tid == 0) {
    lse[row] = M + logf(S);
    if (ent) ent[row] = logf(S) - T2 / S;
    amax[row] = MI;
    int tg = targets[row];
    tgt[row] = HALF ? __half2float(Lh[tg]) : Lf[tg];
  }
}

// ---------------- exit gate ----------------
__global__ void colmean1h(const __half* __restrict__ he1, float* __restrict__ hbar) {
  int d = blockIdx.x * blockDim.x + threadIdx.x;
  int b = blockIdx.y;
  float s = 0.f;
  const __half* p = he1 + (size_t)b * kT * kD;
  for (int t = 0; t < kT; t++) s += __half2float(p[(size_t)t * kD + d]);
  hbar[b * kD + d] = s / (float)kT;
}

__global__ void gate_kernel(const float* __restrict__ hbar, const float* __restrict__ w1,
                            const float* __restrict__ b1, const float* __restrict__ w2,
                            const float* __restrict__ b2, int j) {
  __shared__ float g[kB][64];
  int tid = threadIdx.x;
  if (tid < kB * 64) {
    int b = tid / 64, u = tid % 64;
    float s = 0.f;
    const float* hp = hbar + b * kD;
    const float* wp = w1 + (size_t)u * kD;
    for (int d = 0; d < kD; d++) s += hp[d] * wp[d];
    g[b][u] = fmaxf(s + b1[u], 0.f);
  }
  __syncthreads();
  if (tid < kB) {
    float s = 0.f;
    for (int u = 0; u < 64; u++) s += g[tid][u] * w2[u];
    g_conf[j * kB + tid] = 1.f / (1.f + expf(-(s + b2[0])));
  }
}

// ---------------- loss assembly ----------------
__global__ void loss_kernel(float* __restrict__ loss_out) {
  int tid = threadIdx.x;
  float ce_f = 0.f, ce_e[2] = {0.f, 0.f};
  float ag[2][2] = {{0.f, 0.f}, {0.f, 0.f}};
  float oc[2] = {0.f, 0.f};
  const float maxent = logf((float)kV);
  for (int r = tid; r < kN; r += 256) {
    int fp = g_amax_f[r];
    ce_f += g_lse_f[r] - g_tgt_f[r];
    int b = r / kT;
#pragma unroll
    for (int j = 0; j < 2; j++) {
      ce_e[j] += g_lse_e[j * kN + r] - g_tgt_e[j * kN + r];
      int ep = g_amax_e[j * kN + r];
      if (ep == fp) ag[j][b] += 1.f;
      else oc[j] += (1.f - g_ent_e[j * kN + r] / maxent);
    }
  }
  __shared__ float sh[256];
  float vals[9] = {ce_f, ce_e[0], ce_e[1], ag[0][0], ag[0][1], ag[1][0], ag[1][1], oc[0], oc[1]};
  float red[9];
#pragma unroll
  for (int q = 0; q < 9; q++) {
    sh[tid] = vals[q];
    __syncthreads();
    for (int off = 128; off > 0; off >>= 1) { if (tid < off) sh[tid] += sh[tid + off]; __syncthreads(); }
    red[q] = sh[0];
    __syncthreads();
  }
  if (tid == 0) {
    const float w[2] = {0.3f, 0.5f};
    float loss = red[0] / (float)kN;
    for (int j = 0; j < 2; j++) {
      loss += w[j] * (red[1 + j] / (float)kN);
      float bce = 0.f;
      for (int b = 0; b < kB; b++) {
        float agree = red[3 + j * 2 + b] / (float)kT;
        float c = fminf(fmaxf(g_conf[j * kB + b], 1e-7f), 1.f - 1e-7f);
        bce += -(agree * logf(c) + (1.f - agree) * logf(1.f - c));
      }
      loss += 0.5f * (bce / (float)kB);
      loss += 0.1f * (red[7 + j] / (float)kN);
    }
    loss_out[0] = loss;
  }
}

// ---------------- host orchestration ----------------
#define DSMEM (NST * STAGE_B)  // 61440

extern "C" void kernel_launch(void* const* d_in, const int* in_sizes, int n_in,
                              void* d_out, int out_size) {
  const int* idx = (const int*)d_in[0];
  const int* targets = (const int*)d_in[1];
  const float* embed = (const float*)d_in[2];
  const float* ln_in_w = (const float*)d_in[3];
  const float* ln_in_b = (const float*)d_in[4];
  const float* Wr = (const float*)d_in[5];
  const float* Wk = (const float*)d_in[6];
  const float* Wv = (const float*)d_in[7];
  const float* Wo_tm = (const float*)d_in[8];
  const float* decay = (const float*)d_in[9];
  const float* gn_w = (const float*)d_in[10];
  const float* gn_b = (const float*)d_in[11];
  const float* ln1_w = (const float*)d_in[12];
  const float* ln1_b = (const float*)d_in[13];
  const float* ln2_w = (const float*)d_in[14];
  const float* ln2_b = (const float*)d_in[15];
  const float* W1 = (const float*)d_in[16];
  const float* W2 = (const float*)d_in[17];
  const float* Wo_cm = (const float*)d_in[18];
  const float* ln_out_w = (const float*)d_in[19];
  const float* ln_out_b = (const float*)d_in[20];
  const float* exit_ln_w = (const float*)d_in[21];
  const float* exit_ln_b = (const float*)d_in[22];
  const float* exit_head = (const float*)d_in[23];
  const float* gate_w1 = (const float*)d_in[24];
  const float* gate_b1 = (const float*)d_in[25];
  const float* gate_w2 = (const float*)d_in[26];
  const float* gate_b2 = (const float*)d_in[27];
  float* out = (float*)d_out;

  float *xp, *rkvp, *attp, *elp, *hbarp;
  float *lse_f, *tgt_f, *lse_e, *tgt_e, *ent_e;
  int *amax_f, *amax_e;
  __half *h1p, *ff2hp, *Wrkvh, *Wotmh, *W123h, *Wocmh, *embedh, *exith;
  cudaGetSymbolAddress((void**)&xp, g_x);
  cudaGetSymbolAddress((void**)&rkvp, g_rkv);
  cudaGetSymbolAddress((void**)&attp, g_att);
  cudaGetSymbolAddress((void**)&elp, g_elog);
  cudaGetSymbolAddress((void**)&hbarp, g_hbar);
  cudaGetSymbolAddress((void**)&lse_f, g_lse_f);
  cudaGetSymbolAddress((void**)&tgt_f, g_tgt_f);
  cudaGetSymbolAddress((void**)&amax_f, g_amax_f);
  cudaGetSymbolAddress((void**)&lse_e, g_lse_e);
  cudaGetSymbolAddress((void**)&tgt_e, g_tgt_e);
  cudaGetSymbolAddress((void**)&ent_e, g_ent_e);
  cudaGetSymbolAddress((void**)&amax_e, g_amax_e);
  cudaGetSymbolAddress((void**)&h1p, g_h1);
  cudaGetSymbolAddress((void**)&ff2hp, g_ff2h);
  cudaGetSymbolAddress((void**)&Wrkvh, g_Wrkvh);
  cudaGetSymbolAddress((void**)&Wotmh, g_Wotmh);
  cudaGetSymbolAddress((void**)&W123h, g_W123h);
  cudaGetSymbolAddress((void**)&Wocmh, g_Wocmh);
  cudaGetSymbolAddress((void**)&embedh, g_embedh);
  cudaGetSymbolAddress((void**)&exith, g_exith);

  cudaFuncSetAttribute((const void*)gemm3<0>, cudaFuncAttributeMaxDynamicSharedMemorySize, DSMEM);
  cudaFuncSetAttribute((const void*)gemm3<1>, cudaFuncAttributeMaxDynamicSharedMemorySize, DSMEM);
  cudaFuncSetAttribute((const void*)gemm3<2>, cudaFuncAttributeMaxDynamicSharedMemorySize, DSMEM);
  cudaFuncSetAttribute((const void*)gemm3<3>, cudaFuncAttributeMaxDynamicSharedMemorySize, DSMEM);
  cudaFuncSetAttribute((const void*)gemm3<4>, cudaFuncAttributeMaxDynamicSharedMemorySize, DSMEM);

  dim3 g_rkvg(kN / BM, (3 * kD) / BN);   // (16,24)
  dim3 g_dd(kN / BM, kD / BN);           // (16,8)
  dim3 g_w12(kN / BM, (2 * kDFF) / BN);  // (16,64) over interleaved cols
  dim3 g_vg(kN / BM, kV / BN);           // (16,250)

  const long L4 = 0x7fffffffffffffffL;

  // ---- launch #1: fp16 TimeMix weight conversion (single-term) ----
  {
    ConvArgs a1;
    long t = (long)kL * kD * kD / 4;
    a1.s[0] = {Wr, Wrkvh, kD, kD, 3 * kD, 0, 2, 1, t};
    a1.s[1] = {Wk, Wrkvh, kD, kD, 3 * kD, kD, 2, 1, 2 * t};
    a1.s[2] = {Wv, Wrkvh, kD, kD, 3 * kD, 2 * kD, 2, 1, 3 * t};
    a1.s[3] = {Wo_tm, Wotmh, kD, kL * kD, kL * kD, 0, 2, 1, 4 * t};
    conv_multi<<<(unsigned)((4 * t + 255) / 256), 256>>>(a1, 4 * t);
  }

  // ---- launches #2-#4: embed_ln, ln1(l0), rkv GEMM(l0)  [#4 = ncu target] --
  embed_ln<<<kN, 256>>>(idx, embed, ln_in_w, ln_in_b, xp);
  ln_rows1h<<<kN, 256>>>(xp, h1p, ln1_w, ln1_b);
  gemm3<1><<<g_rkvg, 256, DSMEM>>>(h1p, Wrkvh, rkvp, 3 * kD, kD, kD);

  // ---- remaining weight conversions ----
  {
    ConvArgs a2;  // fp16 single ChannelMix weights (W1/W2 row-interleaved)
    long u = (long)kL * kDFF * kD / 4;
    a2.s[0] = {W1, W123h, kD, kDFF, 2 * kDFF, 0, 2, 2, u};
    a2.s[1] = {W2, W123h, kD, kDFF, 2 * kDFF, 1, 2, 2, 2 * u};
    a2.s[2] = {Wo_cm, Wocmh, kDFF, kL * kD, kL * kD, 0, 2, 1, 3 * u};
    a2.s[3] = {nullptr, nullptr, 4, 1, 1, 0, 2, 1, L4};
    conv_multi<<<(unsigned)((3 * u + 255) / 256), 256>>>(a2, 3 * u);
    ConvArgs a3;  // fp16 single vocab weights
    long e1 = (long)kV * kD / 4, e2 = 2L * kV * kD / 4;
    a3.s[0] = {embed, embedh, kD, kV, kV, 0, 2, 1, e1};
    a3.s[1] = {exit_head, exith, kD, 2 * kV, 2 * kV, 0, 2, 1, e1 + e2};
    a3.s[2] = {nullptr, nullptr, 4, 1, 1, 0, 2, 1, L4};
    a3.s[3] = {nullptr, nullptr, 4, 1, 1, 0, 2, 1, L4};
    conv_multi<<<(unsigned)((e1 + e2 + 255) / 256), 256>>>(a3, e1 + e2);
  }

  for (int i = 0; i < kL; i++) {
    // --- TimeMix (layer 0's ln1+rkv already launched above) ---
    if (i > 0) {
      ln_rows1h<<<kN, 256>>>(xp, h1p, ln1_w + i * kD, ln1_b + i * kD);
      gemm3<1><<<g_rkvg, 256, DSMEM>>>(h1p, Wrkvh + (size_t)i * 3 * kD * kD, rkvp,
                                       3 * kD, kD, kD);
    }
    timemix2<<<kB * (kD / DGRP), dim3(DGRP, TMCH)>>>(rkvp, decay + i * kD, attp);
    gn_reduce<<<kB * 64, 256>>>(attp);
    gn_apply1h<<<dim3(kT * kD / 256, kB), 256>>>(attp, gn_w + i * kD, gn_b + i * kD, h1p);
    gemm3<2><<<g_dd, 256, DSMEM>>>(h1p, Wotmh + (size_t)i * kD * kD, xp, kD, kD, 0);
    // --- ChannelMix (single-term fp16, fused SwiGLU epilogue) ---
    ln_rows1h<<<kN, 256>>>(xp, h1p, ln2_w + i * kD, ln2_b + i * kD);
    gemm3<3><<<g_w12, 256, DSMEM>>>(h1p, W123h + (size_t)i * 2 * kDFF * kD,
                                    (float*)ff2hp, kDFF, kD, 0);
    gemm3<2><<<g_dd, 256, DSMEM>>>(ff2hp, Wocmh + (size_t)i * kD * kDFF,
                                   xp, kD, kDFF, 0);
    // --- early exits (fp16 logits, two-pass stats) ---
    if (i == 3 || i == 7) {
      int j = (i == 3) ? 0 : 1;
      ln_rows1h<<<kN, 256>>>(xp, h1p, exit_ln_w + j * kD, exit_ln_b + j * kD);
      gemm3<4><<<g_vg, 256, DSMEM>>>(h1p, exith + (size_t)j * kV * kD, elp, kV, kD, 0);
      rowstats<1><<<kN, 256>>>(elp, targets, lse_e + j * kN, tgt_e + j * kN,
                               amax_e + j * kN, ent_e + j * kN);
      colmean1h<<<dim3(kD / 256, kB), 256>>>(h1p, hbarp);
      gate_kernel<<<1, 128>>>(hbarp, gate_w1 + (size_t)j * 64 * kD, gate_b1 + j * 64,
                              gate_w2 + j * 64, gate_b2 + j, j);
    }
  }

  // final LN + tied head (fp32 logits into d_out, two-pass stats)
  ln_rows1h<<<kN, 256>>>(xp, h1p, ln_out_w, ln_out_b);
  gemm3<0><<<g_vg, 256, DSMEM>>>(h1p, embedh, out, kV, kD, 0);
  rowstats<0><<<kN, 256>>>(out, targets, lse_f, tgt_f, amax_f, (float*)nullptr);
  loss_kernel<<<1, 256>>>(out + (size_t)kN * kV);
}

// round 16
// speedup vs baseline: 1.1480x; 1.0141x over previous
#include <cuda_runtime.h>
#include <cuda_bf16.h>
#include <cuda_fp16.h>
#include <math.h>
#include <stdint.h>

// ---------------- constants ----------------
#define kB 2
#define kT 1024
#define kD 1024
#define kDFF 4096
#define kV 32000
#define kL 12
#define kN (kB * kT)  // 2048 rows

typedef __nv_bfloat16 bf16;

// ---------------- scratch ----------------
__device__ float g_x[kN * kD];
__device__ float g_rkv[kN * 3 * kD];
__device__ float g_att[kN * kD];
__device__ float g_part[2 * kN * kD];         // split-K partial sums
__device__ float g_elog[(size_t)kN * kV];     // exit logits (fp16, aliased)
__device__ __half g_h1[kN * kD];              // fp16 single A (all GEMM inputs)
__device__ __half g_ff2h[(size_t)kN * kDFF];  // fp16 single A for Wocm (silu output)
// weights: ALL single-term fp16 K'=K. W12 rows interleaved W1/W2.
__device__ __half g_Wrkvh[(size_t)kL * 3 * kD * kD];
__device__ __half g_Wotmh[(size_t)kL * kD * kD];
__device__ __half g_W123h[(size_t)kL * 2 * kDFF * kD];
__device__ __half g_Wocmh[(size_t)kL * kD * kDFF];
__device__ __half g_embedh[(size_t)kV * kD];
__device__ __half g_exith[(size_t)2 * kV * kD];

__device__ double g_gn_part[kB][64][2];
__device__ float g_hbar[kB * kD];
__device__ float g_conf[2 * kB];
__device__ float g_lse_f[kN], g_tgt_f[kN];
__device__ int   g_amax_f[kN];
__device__ float g_lse_e[2 * kN], g_tgt_e[2 * kN], g_ent_e[2 * kN];
__device__ int   g_amax_e[2 * kN];

// ---------------- helpers ----------------
__device__ __forceinline__ uint32_t smem_u32(const void* p) {
  return (uint32_t)__cvta_generic_to_shared(p);
}
__device__ __forceinline__ void cp16(uint32_t s, const void* g) {
  asm volatile("cp.async.ca.shared.global [%0], [%1], 16;\n" ::"r"(s), "l"(g));
}
__device__ __forceinline__ void cp_commit() { asm volatile("cp.async.commit_group;\n"); }
template <int NW>
__device__ __forceinline__ void cp_wait() { asm volatile("cp.async.wait_group %0;\n" ::"n"(NW)); }
__device__ __forceinline__ void ldm_x4(uint32_t* r, uint32_t a) {
  asm volatile("ldmatrix.sync.aligned.m8n8.x4.shared.b16 {%0,%1,%2,%3}, [%4];\n"
               : "=r"(r[0]), "=r"(r[1]), "=r"(r[2]), "=r"(r[3]) : "r"(a));
}
__device__ __forceinline__ void mma_f16(float* d, const uint32_t* a, const uint32_t* b) {
  asm volatile(
      "mma.sync.aligned.m16n8k16.row.col.f32.f16.f16.f32 "
      "{%0,%1,%2,%3}, {%4,%5,%6,%7}, {%8,%9}, {%0,%1,%2,%3};\n"
      : "+f"(d[0]), "+f"(d[1]), "+f"(d[2]), "+f"(d[3])
      : "r"(a[0]), "r"(a[1]), "r"(a[2]), "r"(a[3]), "r"(b[0]), "r"(b[1]));
}

// ---------------- segmented weight conversion ----------------
struct ConvSeg {
  const float* in;
  void* out;
  int K;
  int srcRPL;
  int outRPL;
  int outOff;
  int fmt;      // 2 = single-term fp16
  int rstride;  // output row spacing (2 = interleave)
  long cum;     // cumulative END (in float4 units)
};
struct ConvArgs { ConvSeg s[4]; };

__global__ void conv_multi(ConvArgs a, long grand) {
  long i = (long)blockIdx.x * blockDim.x + threadIdx.x;
  if (i >= grand) return;
  int si = 0;
  while (i >= a.s[si].cum) si++;
  long local = i - (si ? a.s[si - 1].cum : 0L);
  const ConvSeg g = a.s[si];
  int K4 = g.K >> 2;
  long rs = local / K4;
  int c = (int)(local % K4) << 2;
  long layer = rs / g.srcRPL;
  int r = (int)(rs % g.srcRPL);
  long orow = layer * g.outRPL + g.outOff + (long)r * g.rstride;
  float4 v = ((const float4*)g.in)[local];
  float vv[4] = {v.x, v.y, v.z, v.w};
  ushort h[4];
#pragma unroll
  for (int e = 0; e < 4; e++) h[e] = __half_as_ushort(__float2half_rn(vv[e]));
  uint2 hp = {(uint32_t)h[0] | ((uint32_t)h[1] << 16), (uint32_t)h[2] | ((uint32_t)h[3] << 16)};
  __half* ob = (__half*)g.out + orow * (long)g.K;
  *(uint2*)(ob + c) = hp;
}

// ---------------- pipelined fp16 tensor-core GEMM ----------------
// C[n,m] = sum_k A[n,k]*W[m,k], fp16 operands, fp32 accum.
// MODE 0: store fp32. 1: sigmoid where col<sigcut else store (fp32).
// MODE 2: += C (fp32). MODE 3: fused SwiGLU -> fp16 at col gc/2 (M=kDFF).
// MODE 4: store fp16.
#define BM 128
#define BN 128
#define BK 32
#define NST 3
#define LDSB 80  // bytes per smem row (40 elems)
#define STAGE_B ((BM + BN) * LDSB)  // 20480

template <int MODE>
__global__ void __launch_bounds__(256, 2)
gemm3(const __half* __restrict__ A, const __half* __restrict__ W,
      float* __restrict__ C, int M, int Kp, int sigcut) {
  extern __shared__ bf16 dynsmem[];
  uint32_t sbase = smem_u32(dynsmem);

  int tid = threadIdx.x;
  int lane = tid & 31, wid = tid >> 5;
  int wm = wid >> 2, wn = wid & 3;  // 2x4 warps, warp tile 64x32

  const __half* Ab = A + (size_t)(blockIdx.x * BM) * Kp;
  const __half* Wb = W + (size_t)(blockIdx.y * BN) * Kp;

  int r0 = tid >> 2, c0 = (tid & 3);
  int r1 = (tid + 256) >> 2, c1 = (tid & 3);

  float acc[4][4][4];
#pragma unroll
  for (int i = 0; i < 4; i++)
#pragma unroll
    for (int j = 0; j < 4; j++)
#pragma unroll
      for (int q = 0; q < 4; q++) acc[i][j][q] = 0.f;

  int KT = Kp / BK;

  int laneA = (wm * 64 + (lane & 7) + ((lane >> 3) & 1) * 8) * LDSB + ((lane >> 4)) * 16;
  int laneW = BM * LDSB + (wn * 32 + (lane & 7) + (lane >> 4) * 8) * LDSB +
              (((lane >> 3) & 1)) * 16;

#define ISSUE(stage, kt)                                                            \
  {                                                                                 \
    uint32_t sb = sbase + (uint32_t)(stage) * STAGE_B;                              \
    const __half* ga = Ab + (size_t)(kt) * BK;                                      \
    const __half* gw = Wb + (size_t)(kt) * BK;                                      \
    cp16(sb + r0 * LDSB + c0 * 16, ga + (size_t)r0 * Kp + c0 * 8);                  \
    cp16(sb + r1 * LDSB + c1 * 16, ga + (size_t)r1 * Kp + c1 * 8);                  \
    cp16(sb + BM * LDSB + r0 * LDSB + c0 * 16, gw + (size_t)r0 * Kp + c0 * 8);      \
    cp16(sb + BM * LDSB + r1 * LDSB + c1 * 16, gw + (size_t)r1 * Kp + c1 * 8);      \
  }

  ISSUE(0, 0); cp_commit();
  ISSUE(1, 1); cp_commit();

  for (int kt = 0; kt < KT; kt++) {
    cp_wait<1>();
    __syncthreads();
    int st = kt % NST;
    if (kt + 2 < KT) { ISSUE((kt + 2) % NST, kt + 2); }
    cp_commit();

    uint32_t stA = sbase + st * STAGE_B + laneA;
    uint32_t stW = sbase + st * STAGE_B + laneW;
#pragma unroll
    for (int kk = 0; kk < 2; kk++) {
      uint32_t b[8];
      ldm_x4(b, stW + kk * 32);
      ldm_x4(b + 4, stW + 16 * LDSB + kk * 32);
#pragma unroll
      for (int mt = 0; mt < 4; mt++) {
        uint32_t a[4];
        ldm_x4(a, stA + mt * 16 * LDSB + kk * 32);
#pragma unroll
        for (int nt = 0; nt < 4; nt++) mma_f16(acc[mt][nt], a, b + nt * 2);
      }
    }
  }
#undef ISSUE

  // epilogue
#pragma unroll
  for (int mt = 0; mt < 4; mt++) {
#pragma unroll
    for (int nt = 0; nt < 4; nt++) {
      int gr0 = blockIdx.x * BM + wm * 64 + mt * 16 + (lane >> 2);
      int gc = blockIdx.y * BN + wn * 32 + nt * 8 + ((lane & 3) << 1);
#pragma unroll
      for (int half = 0; half < 2; half++) {
        int gr = gr0 + half * 8;
        float v0 = acc[mt][nt][half * 2 + 0];
        float v1 = acc[mt][nt][half * 2 + 1];
        if (MODE == 3) {
          float y = (v0 / (1.f + expf(-v0))) * v1;
          __half* oh = (__half*)C;
          oh[(size_t)gr * M + (gc >> 1)] = __float2half_rn(y);
        } else if (MODE == 4) {
          __half* oh = (__half*)C;
          size_t off = (size_t)gr * M + gc;
          __half2 o2h = {__float2half_rn(v0), __float2half_rn(v1)};
          *(__half2*)&oh[off] = o2h;
        } else {
          size_t off = (size_t)gr * M + gc;
          if (MODE == 1) {
            if (gc < sigcut) {
              v0 = 1.f / (1.f + expf(-v0));
              v1 = 1.f / (1.f + expf(-v1));
            }
          } else if (MODE == 2) {
            float2 old = *(const float2*)&C[off];
            v0 += old.x; v1 += old.y;
          }
          float2 o2 = {v0, v1};
          *(float2*)&C[off] = o2;
        }
      }
    }
  }
}

// ---------------- split-K GEMM: gridDim.z slices of K, partial fp32 out -----
// P[z][n][m] = sum_{k in slice z} A[n,k]*W[m,k]; row stride = `stride` elems.
__global__ void __launch_bounds__(256, 2)
gemm_sk(const __half* __restrict__ A, const __half* __restrict__ W,
        float* __restrict__ P, int M, int Khalf, int stride) {
  extern __shared__ bf16 dynsmem[];
  uint32_t sbase = smem_u32(dynsmem);

  int tid = threadIdx.x;
  int lane = tid & 31, wid = tid >> 5;
  int wm = wid >> 2, wn = wid & 3;

  int koff = blockIdx.z * Khalf;
  const __half* Ab = A + (size_t)(blockIdx.x * BM) * stride + koff;
  const __half* Wb = W + (size_t)(blockIdx.y * BN) * stride + koff;
  float* Pb = P + (size_t)blockIdx.z * gridDim.x * BM * M;

  int r0 = tid >> 2, c0 = (tid & 3);
  int r1 = (tid + 256) >> 2, c1 = (tid & 3);

  float acc[4][4][4];
#pragma unroll
  for (int i = 0; i < 4; i++)
#pragma unroll
    for (int j = 0; j < 4; j++)
#pragma unroll
      for (int q = 0; q < 4; q++) acc[i][j][q] = 0.f;

  int KT = Khalf / BK;

  int laneA = (wm * 64 + (lane & 7) + ((lane >> 3) & 1) * 8) * LDSB + ((lane >> 4)) * 16;
  int laneW = BM * LDSB + (wn * 32 + (lane & 7) + (lane >> 4) * 8) * LDSB +
              (((lane >> 3) & 1)) * 16;

#define ISSUE2(stage, kt)                                                              \
  {                                                                                    \
    uint32_t sb = sbase + (uint32_t)(stage) * STAGE_B;                                 \
    const __half* ga = Ab + (size_t)(kt) * BK;                                         \
    const __half* gw = Wb + (size_t)(kt) * BK;                                         \
    cp16(sb + r0 * LDSB + c0 * 16, ga + (size_t)r0 * stride + c0 * 8);                 \
    cp16(sb + r1 * LDSB + c1 * 16, ga + (size_t)r1 * stride + c1 * 8);                 \
    cp16(sb + BM * LDSB + r0 * LDSB + c0 * 16, gw + (size_t)r0 * stride + c0 * 8);     \
    cp16(sb + BM * LDSB + r1 * LDSB + c1 * 16, gw + (size_t)r1 * stride + c1 * 8);     \
  }

  ISSUE2(0, 0); cp_commit();
  ISSUE2(1, 1); cp_commit();

  for (int kt = 0; kt < KT; kt++) {
    cp_wait<1>();
    __syncthreads();
    int st = kt % NST;
    if (kt + 2 < KT) { ISSUE2((kt + 2) % NST, kt + 2); }
    cp_commit();

    uint32_t stA = sbase + st * STAGE_B + laneA;
    uint32_t stW = sbase + st * STAGE_B + laneW;
#pragma unroll
    for (int kk = 0; kk < 2; kk++) {
      uint32_t b[8];
      ldm_x4(b, stW + kk * 32);
      ldm_x4(b + 4, stW + 16 * LDSB + kk * 32);
#pragma unroll
      for (int mt = 0; mt < 4; mt++) {
        uint32_t a[4];
        ldm_x4(a, stA + mt * 16 * LDSB + kk * 32);
#pragma unroll
        for (int nt = 0; nt < 4; nt++) mma_f16(acc[mt][nt], a, b + nt * 2);
      }
    }
  }
#undef ISSUE2

#pragma unroll
  for (int mt = 0; mt < 4; mt++) {
#pragma unroll
    for (int nt = 0; nt < 4; nt++) {
      int gr0 = blockIdx.x * BM + wm * 64 + mt * 16 + (lane >> 2);
      int gc = blockIdx.y * BN + wn * 32 + nt * 8 + ((lane & 3) << 1);
#pragma unroll
      for (int half = 0; half < 2; half++) {
        int gr = gr0 + half * 8;
        size_t off = (size_t)gr * M + gc;
        float2 o2 = {acc[mt][nt][half * 2 + 0], acc[mt][nt][half * 2 + 1]};
        *(float2*)&Pb[off] = o2;
      }
    }
  }
}

// x += p0 + p1 (fixed-order, deterministic)
__global__ void add2res(const float* __restrict__ p, float* __restrict__ x) {
  size_t i = (size_t)blockIdx.x * blockDim.x + threadIdx.x;  // float4 index
  float4 a = ((const float4*)p)[i];
  float4 b = ((const float4*)(p + (size_t)kN * kD))[i];
  float4 c = ((float4*)x)[i];
  c.x += a.x + b.x;
  c.y += a.y + b.y;
  c.z += a.z + b.z;
  c.w += a.w + b.w;
  ((float4*)x)[i] = c;
}

// ---------------- LayerNorm ----------------
__device__ __forceinline__ void ln_stats(const float* __restrict__ x, float& mean,
                                         float& rstd) {
  int tid = threadIdx.x;
  float s = 0.f, ss = 0.f;
  for (int i = tid; i < kD; i += 256) { float v = x[i]; s += v; ss += v * v; }
  __shared__ float shs[32], shss[32];
  for (int off = 16; off; off >>= 1) {
    s += __shfl_down_sync(0xffffffffu, s, off);
    ss += __shfl_down_sync(0xffffffffu, ss, off);
  }
  if ((tid & 31) == 0) { shs[tid >> 5] = s; shss[tid >> 5] = ss; }
  __syncthreads();
  if (tid < 32) {
    s = tid < 8 ? shs[tid] : 0.f;
    ss = tid < 8 ? shss[tid] : 0.f;
    for (int off = 4; off; off >>= 1) {
      s += __shfl_down_sync(0xffffffffu, s, off);
      ss += __shfl_down_sync(0xffffffffu, ss, off);
    }
    if (tid == 0) { shs[0] = s; shss[0] = ss; }
  }
  __syncthreads();
  mean = shs[0] / (float)kD;
  float var = shss[0] / (float)kD - mean * mean;
  rstd = rsqrtf(var + 1e-5f);
}

__global__ void ln_rows1h(const float* __restrict__ in, __half* __restrict__ out1,
                          const float* __restrict__ w, const float* __restrict__ bb) {
  size_t row = blockIdx.x;
  const float* x = in + row * kD;
  float mean, rstd;
  ln_stats(x, mean, rstd);
  __half* ob = out1 + row * kD;
  for (int i = threadIdx.x; i < kD; i += 256) {
    float y = (x[i] - mean) * rstd * w[i] + bb[i];
    ob[i] = __float2half_rn(y);
  }
}

__global__ void embed_ln(const int* __restrict__ idx, const float* __restrict__ embed,
                         const float* __restrict__ w, const float* __restrict__ bb,
                         float* __restrict__ out) {
  size_t row = blockIdx.x;
  const float* x = embed + (size_t)idx[row] * kD;
  float mean, rstd;
  ln_stats(x, mean, rstd);
  float* o = out + row * kD;
  for (int i = threadIdx.x; i < kD; i += 256)
    o[i] = (x[i] - mean) * rstd * w[i] + bb[i];
}

// ---------------- TimeMix decay scan (R13-proven) ----------------
#define TMCH 32
#define DGRP 8
__global__ void timemix2(const float* __restrict__ rkv, const float* __restrict__ decay_l,
                         float* __restrict__ out) {
  int b = blockIdx.x / (kD / DGRP);
  int dg = blockIdx.x % (kD / DGRP);
  int d = dg * DGRP + threadIdx.x;
  int chunk = threadIdx.y;
  const int clen = kT / TMCH;
  int t0 = chunk * clen;

  float dec = 1.f / (1.f + expf(-decay_l[d]));
  float logdec = logf(fmaxf(dec, 1e-7f));
  size_t base = (size_t)b * kT * 3 * kD;
  const float* rp = rkv + base + d;
  const float* kp = rkv + base + kD + d;
  const float* vp = rkv + base + 2 * kD + d;
  float* op = out + (size_t)b * kT * kD + d;

  float s = 0.f;
  for (int t = t0; t < t0 + clen; t++) {
    float scale = __expf((float)t * logdec);
    float denom = fmaxf(scale, 1e-10f);
    s += __fdividef(kp[(size_t)t * 3 * kD] * vp[(size_t)t * 3 * kD], denom);
  }
  __shared__ float cs[TMCH][DGRP];
  cs[chunk][threadIdx.x] = s;
  __syncthreads();
  float cum = 0.f;
  for (int c = 0; c < chunk; c++) cum += cs[c][threadIdx.x];
  for (int t = t0; t < t0 + clen; t++) {
    float scale = __expf((float)t * logdec);
    float denom = fmaxf(scale, 1e-10f);
    cum += __fdividef(kp[(size_t)t * 3 * kD] * vp[(size_t)t * 3 * kD], denom);
    op[(size_t)t * kD] = rp[(size_t)t * 3 * kD] * (cum * scale);
  }
}

// ---------------- GroupNorm(1,D) over (T,D) per batch (partials) -----------
__global__ void gn_reduce(const float* __restrict__ in) {
  const int CH = 64;
  int b = blockIdx.x / CH, chunk = blockIdx.x % CH;
  const int n = kT * kD / CH;
  const float* p = in + (size_t)b * kT * kD + (size_t)chunk * n;
  double s = 0.0, ss = 0.0;
  for (int i = threadIdx.x; i < n; i += blockDim.x) {
    double v = (double)p[i];
    s += v; ss += v * v;
  }
  __shared__ double sh1[32], sh2[32];
  for (int off = 16; off; off >>= 1) {
    s += __shfl_down_sync(0xffffffffu, s, off);
    ss += __shfl_down_sync(0xffffffffu, ss, off);
  }
  int tid = threadIdx.x;
  if ((tid & 31) == 0) { sh1[tid >> 5] = s; sh2[tid >> 5] = ss; }
  __syncthreads();
  int nw = (blockDim.x + 31) >> 5;
  if (tid < 32) {
    s = tid < nw ? sh1[tid] : 0.0;
    ss = tid < nw ? sh2[tid] : 0.0;
    for (int off = 16; off; off >>= 1) {
      s += __shfl_down_sync(0xffffffffu, s, off);
      ss += __shfl_down_sync(0xffffffffu, ss, off);
    }
    if (tid == 0) { g_gn_part[b][chunk][0] = s; g_gn_part[b][chunk][1] = ss; }
  }
}

// GN apply -> fp16 single A-layout (for Wotm GEMM)
__global__ void gn_apply1h(const float* __restrict__ in, const float* __restrict__ gw,
                           const float* __restrict__ gb, __half* __restrict__ out1) {
  int b = blockIdx.y;
  __shared__ float sh_m, sh_r;
  if (threadIdx.x == 0) {
    double s = 0.0, ss = 0.0;
    for (int c2 = 0; c2 < 64; c2++) { s += g_gn_part[b][c2][0]; ss += g_gn_part[b][c2][1]; }
    double inv = 1.0 / (double)(kT * kD);
    double m = s * inv;
    double var = ss * inv - m * m;
    sh_m = (float)m;
    sh_r = rsqrtf((float)var + 1e-5f);
  }
  __syncthreads();
  int idx = blockIdx.x * blockDim.x + threadIdx.x;
  int d = idx & (kD - 1);
  size_t row = (size_t)b * kT + (idx >> 10);
  float y = (in[(size_t)b * kT * kD + idx] - sh_m) * sh_r * gw[d] + gb[d];
  out1[row * kD + d] = __float2half_rn(y);
}

// ---------------- per-row logit stats (two-pass) ----------------
// HALF=0: fp32 logits. HALF=1: fp16 logits.
template <int HALF>
__global__ void rowstats(const void* __restrict__ logits, const int* __restrict__ targets,
                         float* __restrict__ lse, float* __restrict__ tgt,
                         int* __restrict__ amax, float* __restrict__ ent) {
  int row = blockIdx.x;
  int tid = threadIdx.x;
  const float* Lf = (const float*)logits + (size_t)row * kV;
  const __half* Lh = (const __half*)logits + (size_t)row * kV;

  __shared__ float svals[256];
  __shared__ int sidx[256];
  float m = -3.4e38f; int mi = 0;
  for (int i = tid; i < kV; i += 256) {
    float v = HALF ? __half2float(Lh[i]) : Lf[i];
    if (v > m) { m = v; mi = i; }
  }
  svals[tid] = m; sidx[tid] = mi;
  __syncthreads();
  for (int off = 128; off > 0; off >>= 1) {
    if (tid < off) {
      float v2 = svals[tid + off]; int i2 = sidx[tid + off];
      if (v2 > svals[tid] || (v2 == svals[tid] && i2 < sidx[tid])) { svals[tid] = v2; sidx[tid] = i2; }
    }
    __syncthreads();
  }
  float M = svals[0]; int MI = sidx[0];
  __syncthreads();
  float s = 0.f, t2 = 0.f;
  for (int i = tid; i < kV; i += 256) {
    float v = (HALF ? __half2float(Lh[i]) : Lf[i]) - M;
    float e = __expf(v);
    s += e; t2 += e * v;
  }
  svals[tid] = s; __syncthreads();
  for (int off = 128; off > 0; off >>= 1) { if (tid < off) svals[tid] += svals[tid + off]; __syncthreads(); }
  float S = svals[0]; __syncthreads();
  svals[tid] = t2; __syncthreads();
  for (int off = 128; off > 0; off >>= 1) { if (tid < off) svals[tid] += svals[tid + off]; __syncthreads(); }
  float T2 = svals[0];
  if (tid == 0) {
    lse[row] = M + logf(S);
    if (ent) ent[row] = logf(S) - T2 / S;
    amax[row] = MI;
    int tg = targets[row];
    tgt[row] = HALF ? __half2float(Lh[tg]) : Lf[tg];
  }
}

// ---------------- exit gate ----------------
__global__ void colmean1h(const __half* __restrict__ he1, float* __restrict__ hbar) {
  int d = blockIdx.x * blockDim.x + threadIdx.x;
  int b = blockIdx.y;
  float s = 0.f;
  const __half* p = he1 + (size_t)b * kT * kD;
  for (int t = 0; t < kT; t++) s += __half2float(p[(size_t)t * kD + d]);
  hbar[b * kD + d] = s / (float)kT;
}

__global__ void gate_kernel(const float* __restrict__ hbar, const float* __restrict__ w1,
                            const float* __restrict__ b1, const float* __restrict__ w2,
                            const float* __restrict__ b2, int j) {
  __shared__ float g[kB][64];
  int tid = threadIdx.x;
  if (tid < kB * 64) {
    int b = tid / 64, u = tid % 64;
    float s = 0.f;
    const float* hp = hbar + b * kD;
    const float* wp = w1 + (size_t)u * kD;
    for (int d = 0; d < kD; d++) s += hp[d] * wp[d];
    g[b][u] = fmaxf(s + b1[u], 0.f);
  }
  __syncthreads();
  if (tid < kB) {
    float s = 0.f;
    for (int u = 0; u < 64; u++) s += g[tid][u] * w2[u];
    g_conf[j * kB + tid] = 1.f / (1.f + expf(-(s + b2[0])));
  }
}

// ---------------- loss assembly ----------------
__global__ void loss_kernel(float* __restrict__ loss_out) {
  int tid = threadIdx.x;
  float ce_f = 0.f, ce_e[2] = {0.f, 0.f};
  float ag[2][2] = {{0.f, 0.f}, {0.f, 0.f}};
  float oc[2] = {0.f, 0.f};
  const float maxent = logf((float)kV);
  for (int r = tid; r < kN; r += 256) {
    int fp = g_amax_f[r];
    ce_f += g_lse_f[r] - g_tgt_f[r];
    int b = r / kT;
#pragma unroll
    for (int j = 0; j < 2; j++) {
      ce_e[j] += g_lse_e[j * kN + r] - g_tgt_e[j * kN + r];
      int ep = g_amax_e[j * kN + r];
      if (ep == fp) ag[j][b] += 1.f;
      else oc[j] += (1.f - g_ent_e[j * kN + r] / maxent);
    }
  }
  __shared__ float sh[256];
  float vals[9] = {ce_f, ce_e[0], ce_e[1], ag[0][0], ag[0][1], ag[1][0], ag[1][1], oc[0], oc[1]};
  float red[9];
#pragma unroll
  for (int q = 0; q < 9; q++) {
    sh[tid] = vals[q];
    __syncthreads();
    for (int off = 128; off > 0; off >>= 1) { if (tid < off) sh[tid] += sh[tid + off]; __syncthreads(); }
    red[q] = sh[0];
    __syncthreads();
  }
  if (tid == 0) {
    const float w[2] = {0.3f, 0.5f};
    float loss = red[0] / (float)kN;
    for (int j = 0; j < 2; j++) {
      loss += w[j] * (red[1 + j] / (float)kN);
      float bce = 0.f;
      for (int b = 0; b < kB; b++) {
        float agree = red[3 + j * 2 + b] / (float)kT;
        float c = fminf(fmaxf(g_conf[j * kB + b], 1e-7f), 1.f - 1e-7f);
        bce += -(agree * logf(c) + (1.f - agree) * logf(1.f - c));
      }
      loss += 0.5f * (bce / (float)kB);
      loss += 0.1f * (red[7 + j] / (float)kN);
    }
    loss_out[0] = loss;
  }
}

// ---------------- host orchestration ----------------
#define DSMEM (NST * STAGE_B)  // 61440

extern "C" void kernel_launch(void* const* d_in, const int* in_sizes, int n_in,
                              void* d_out, int out_size) {
  const int* idx = (const int*)d_in[0];
  const int* targets = (const int*)d_in[1];
  const float* embed = (const float*)d_in[2];
  const float* ln_in_w = (const float*)d_in[3];
  const float* ln_in_b = (const float*)d_in[4];
  const float* Wr = (const float*)d_in[5];
  const float* Wk = (const float*)d_in[6];
  const float* Wv = (const float*)d_in[7];
  const float* Wo_tm = (const float*)d_in[8];
  const float* decay = (const float*)d_in[9];
  const float* gn_w = (const float*)d_in[10];
  const float* gn_b = (const float*)d_in[11];
  const float* ln1_w = (const float*)d_in[12];
  const float* ln1_b = (const float*)d_in[13];
  const float* ln2_w = (const float*)d_in[14];
  const float* ln2_b = (const float*)d_in[15];
  const float* W1 = (const float*)d_in[16];
  const float* W2 = (const float*)d_in[17];
  const float* Wo_cm = (const float*)d_in[18];
  const float* ln_out_w = (const float*)d_in[19];
  const float* ln_out_b = (const float*)d_in[20];
  const float* exit_ln_w = (const float*)d_in[21];
  const float* exit_ln_b = (const float*)d_in[22];
  const float* exit_head = (const float*)d_in[23];
  const float* gate_w1 = (const float*)d_in[24];
  const float* gate_b1 = (const float*)d_in[25];
  const float* gate_w2 = (const float*)d_in[26];
  const float* gate_b2 = (const float*)d_in[27];
  float* out = (float*)d_out;

  float *xp, *rkvp, *attp, *partp, *elp, *hbarp;
  float *lse_f, *tgt_f, *lse_e, *tgt_e, *ent_e;
  int *amax_f, *amax_e;
  __half *h1p, *ff2hp, *Wrkvh, *Wotmh, *W123h, *Wocmh, *embedh, *exith;
  cudaGetSymbolAddress((void**)&xp, g_x);
  cudaGetSymbolAddress((void**)&rkvp, g_rkv);
  cudaGetSymbolAddress((void**)&attp, g_att);
  cudaGetSymbolAddress((void**)&partp, g_part);
  cudaGetSymbolAddress((void**)&elp, g_elog);
  cudaGetSymbolAddress((void**)&hbarp, g_hbar);
  cudaGetSymbolAddress((void**)&lse_f, g_lse_f);
  cudaGetSymbolAddress((void**)&tgt_f, g_tgt_f);
  cudaGetSymbolAddress((void**)&amax_f, g_amax_f);
  cudaGetSymbolAddress((void**)&lse_e, g_lse_e);
  cudaGetSymbolAddress((void**)&tgt_e, g_tgt_e);
  cudaGetSymbolAddress((void**)&ent_e, g_ent_e);
  cudaGetSymbolAddress((void**)&amax_e, g_amax_e);
  cudaGetSymbolAddress((void**)&h1p, g_h1);
  cudaGetSymbolAddress((void**)&ff2hp, g_ff2h);
  cudaGetSymbolAddress((void**)&Wrkvh, g_Wrkvh);
  cudaGetSymbolAddress((void**)&Wotmh, g_Wotmh);
  cudaGetSymbolAddress((void**)&W123h, g_W123h);
  cudaGetSymbolAddress((void**)&Wocmh, g_Wocmh);
  cudaGetSymbolAddress((void**)&embedh, g_embedh);
  cudaGetSymbolAddress((void**)&exith, g_exith);

  cudaFuncSetAttribute((const void*)gemm3<0>, cudaFuncAttributeMaxDynamicSharedMemorySize, DSMEM);
  cudaFuncSetAttribute((const void*)gemm3<1>, cudaFuncAttributeMaxDynamicSharedMemorySize, DSMEM);
  cudaFuncSetAttribute((const void*)gemm3<3>, cudaFuncAttributeMaxDynamicSharedMemorySize, DSMEM);
  cudaFuncSetAttribute((const void*)gemm3<4>, cudaFuncAttributeMaxDynamicSharedMemorySize, DSMEM);
  cudaFuncSetAttribute((const void*)gemm_sk, cudaFuncAttributeMaxDynamicSharedMemorySize, DSMEM);

  dim3 g_rkvg(kN / BM, (3 * kD) / BN);     // (16,24)
  dim3 g_ddsk(kN / BM, kD / BN, 2);        // (16,8,2) split-K
  dim3 g_w12(kN / BM, (2 * kDFF) / BN);    // (16,64)
  dim3 g_vg(kN / BM, kV / BN);             // (16,250)

  const long L4 = 0x7fffffffffffffffL;

  // ---- launch #1: fp16 TimeMix weight conversion (single-term) ----
  {
    ConvArgs a1;
    long t = (long)kL * kD * kD / 4;
    a1.s[0] = {Wr, Wrkvh, kD, kD, 3 * kD, 0, 2, 1, t};
    a1.s[1] = {Wk, Wrkvh, kD, kD, 3 * kD, kD, 2, 1, 2 * t};
    a1.s[2] = {Wv, Wrkvh, kD, kD, 3 * kD, 2 * kD, 2, 1, 3 * t};
    a1.s[3] = {Wo_tm, Wotmh, kD, kL * kD, kL * kD, 0, 2, 1, 4 * t};
    conv_multi<<<(unsigned)((4 * t + 255) / 256), 256>>>(a1, 4 * t);
  }

  // ---- launches #2-#4: embed_ln, ln1(l0), rkv GEMM(l0)  [#4 = ncu target] --
  embed_ln<<<kN, 256>>>(idx, embed, ln_in_w, ln_in_b, xp);
  ln_rows1h<<<kN, 256>>>(xp, h1p, ln1_w, ln1_b);
  gemm3<1><<<g_rkvg, 256, DSMEM>>>(h1p, Wrkvh, rkvp, 3 * kD, kD, kD);

  // ---- remaining weight conversions ----
  {
    ConvArgs a2;  // fp16 single ChannelMix weights (W1/W2 row-interleaved)
    long u = (long)kL * kDFF * kD / 4;
    a2.s[0] = {W1, W123h, kD, kDFF, 2 * kDFF, 0, 2, 2, u};
    a2.s[1] = {W2, W123h, kD, kDFF, 2 * kDFF, 1, 2, 2, 2 * u};
    a2.s[2] = {Wo_cm, Wocmh, kDFF, kL * kD, kL * kD, 0, 2, 1, 3 * u};
    a2.s[3] = {nullptr, nullptr, 4, 1, 1, 0, 2, 1, L4};
    conv_multi<<<(unsigned)((3 * u + 255) / 256), 256>>>(a2, 3 * u);
    ConvArgs a3;  // fp16 single vocab weights
    long e1 = (long)kV * kD / 4, e2 = 2L * kV * kD / 4;
    a3.s[0] = {embed, embedh, kD, kV, kV, 0, 2, 1, e1};
    a3.s[1] = {exit_head, exith, kD, 2 * kV, 2 * kV, 0, 2, 1, e1 + e2};
    a3.s[2] = {nullptr, nullptr, 4, 1, 1, 0, 2, 1, L4};
    a3.s[3] = {nullptr, nullptr, 4, 1, 1, 0, 2, 1, L4};
    conv_multi<<<(unsigned)((e1 + e2 + 255) / 256), 256>>>(a3, e1 + e2);
  }

  for (int i = 0; i < kL; i++) {
    // --- TimeMix (layer 0's ln1+rkv already launched above) ---
    if (i > 0) {
      ln_rows1h<<<kN, 256>>>(xp, h1p, ln1_w + i * kD, ln1_b + i * kD);
      gemm3<1><<<g_rkvg, 256, DSMEM>>>(h1p, Wrkvh + (size_t)i * 3 * kD * kD, rkvp,
                                       3 * kD, kD, kD);
    }
    timemix2<<<kB * (kD / DGRP), dim3(DGRP, TMCH)>>>(rkvp, decay + i * kD, attp);
    gn_reduce<<<kB * 64, 256>>>(attp);
    gn_apply1h<<<dim3(kT * kD / 256, kB), 256>>>(attp, gn_w + i * kD, gn_b + i * kD, h1p);
    gemm_sk<<<g_ddsk, 256, DSMEM>>>(h1p, Wotmh + (size_t)i * kD * kD, partp,
                                    kD, 512, kD);
    add2res<<<kN * kD / 1024, 256>>>(partp, xp);
    // --- ChannelMix (single-term fp16, fused SwiGLU epilogue) ---
    ln_rows1h<<<kN, 256>>>(xp, h1p, ln2_w + i * kD, ln2_b + i * kD);
    gemm3<3><<<g_w12, 256, DSMEM>>>(h1p, W123h + (size_t)i * 2 * kDFF * kD,
                                    (float*)ff2hp, kDFF, kD, 0);
    gemm_sk<<<g_ddsk, 256, DSMEM>>>(ff2hp, Wocmh + (size_t)i * kD * kDFF, partp,
                                    kD, 2048, kDFF);
    add2res<<<kN * kD / 1024, 256>>>(partp, xp);
    // --- early exits (fp16 logits, two-pass stats) ---
    if (i == 3 || i == 7) {
      int j = (i == 3) ? 0 : 1;
      ln_rows1h<<<kN, 256>>>(xp, h1p, exit_ln_w + j * kD, exit_ln_b + j * kD);
      gemm3<4><<<g_vg, 256, DSMEM>>>(h1p, exith + (size_t)j * kV * kD, elp, kV, kD, 0);
      rowstats<1><<<kN, 256>>>(elp, targets, lse_e + j * kN, tgt_e + j * kN,
                               amax_e + j * kN, ent_e + j * kN);
      colmean1h<<<dim3(kD / 256, kB), 256>>>(h1p, hbarp);
      gate_kernel<<<1, 128>>>(hbarp, gate_w1 + (size_t)j * 64 * kD, gate_b1 + j * 64,
                              gate_w2 + j * 64, gate_b2 + j, j);
    }
  }

  // final LN + tied head (fp32 logits into d_out, two-pass stats)
  ln_rows1h<<<kN, 256>>>(xp, h1p, ln_out_w, ln_out_b);
  gemm3<0><<<g_vg, 256, DSMEM>>>(h1p, embedh, out, kV, kD, 0);
  rowstats<0><<<kN, 256>>>(out, targets, lse_f, tgt_f, amax_f, (float*)nullptr);
  loss_kernel<<<1, 256>>>(out + (size_t)kN * kV);
}

// round 17
// speedup vs baseline: 1.1708x; 1.0198x over previous
#include <cuda_runtime.h>
#include <cuda_bf16.h>
#include <cuda_fp16.h>
#include <math.h>
#include <stdint.h>

// ---------------- constants ----------------
#define kB 2
#define kT 1024
#define kD 1024
#define kDFF 4096
#define kV 32000
#define kL 12
#define kN (kB * kT)  // 2048 rows

typedef __nv_bfloat16 bf16;

// ---------------- scratch ----------------
__device__ float g_x[kN * kD];
__device__ float g_rkv[kN * 3 * kD];
__device__ float g_att[kN * kD];
__device__ float g_part[2 * kN * kD];         // split-K partial sums
__device__ float g_elog[(size_t)kN * kV];     // exit logits (fp16, aliased)
__device__ __half g_h1[kN * kD];              // fp16 single A (all GEMM inputs)
__device__ __half g_ff2h[(size_t)kN * kDFF];  // fp16 single A for Wocm (silu output)
// weights: ALL single-term fp16 K'=K. W12 rows interleaved W1/W2.
__device__ __half g_Wrkvh[(size_t)kL * 3 * kD * kD];
__device__ __half g_Wotmh[(size_t)kL * kD * kD];
__device__ __half g_W123h[(size_t)kL * 2 * kDFF * kD];
__device__ __half g_Wocmh[(size_t)kL * kD * kDFF];
__device__ __half g_embedh[(size_t)kV * kD];
__device__ __half g_exith[(size_t)2 * kV * kD];

__device__ double g_gn_part[kB][64][2];
__device__ float g_hbar[kB * kD];
__device__ float g_conf[2 * kB];
__device__ float g_lse_f[kN], g_tgt_f[kN];
__device__ int   g_amax_f[kN];
__device__ float g_lse_e[2 * kN], g_tgt_e[2 * kN], g_ent_e[2 * kN];
__device__ int   g_amax_e[2 * kN];

// ---------------- helpers ----------------
__device__ __forceinline__ uint32_t smem_u32(const void* p) {
  return (uint32_t)__cvta_generic_to_shared(p);
}
__device__ __forceinline__ void cp16(uint32_t s, const void* g) {
  asm volatile("cp.async.ca.shared.global [%0], [%1], 16;\n" ::"r"(s), "l"(g));
}
__device__ __forceinline__ void cp_commit() { asm volatile("cp.async.commit_group;\n"); }
template <int NW>
__device__ __forceinline__ void cp_wait() { asm volatile("cp.async.wait_group %0;\n" ::"n"(NW)); }
__device__ __forceinline__ void ldm_x4(uint32_t* r, uint32_t a) {
  asm volatile("ldmatrix.sync.aligned.m8n8.x4.shared.b16 {%0,%1,%2,%3}, [%4];\n"
               : "=r"(r[0]), "=r"(r[1]), "=r"(r[2]), "=r"(r[3]) : "r"(a));
}
__device__ __forceinline__ void mma_f16(float* d, const uint32_t* a, const uint32_t* b) {
  asm volatile(
      "mma.sync.aligned.m16n8k16.row.col.f32.f16.f16.f32 "
      "{%0,%1,%2,%3}, {%4,%5,%6,%7}, {%8,%9}, {%0,%1,%2,%3};\n"
      : "+f"(d[0]), "+f"(d[1]), "+f"(d[2]), "+f"(d[3])
      : "r"(a[0]), "r"(a[1]), "r"(a[2]), "r"(a[3]), "r"(b[0]), "r"(b[1]));
}

// ---------------- segmented weight conversion ----------------
struct ConvSeg {
  const float* in;
  void* out;
  int K;
  int srcRPL;
  int outRPL;
  int outOff;
  int fmt;      // 2 = single-term fp16
  int rstride;  // output row spacing (2 = interleave)
  long cum;     // cumulative END (in float4 units)
};
struct ConvArgs { ConvSeg s[4]; };

__global__ void conv_multi(ConvArgs a, long grand) {
  long i = (long)blockIdx.x * blockDim.x + threadIdx.x;
  if (i >= grand) return;
  int si = 0;
  while (i >= a.s[si].cum) si++;
  long local = i - (si ? a.s[si - 1].cum : 0L);
  const ConvSeg g = a.s[si];
  int K4 = g.K >> 2;
  long rs = local / K4;
  int c = (int)(local % K4) << 2;
  long layer = rs / g.srcRPL;
  int r = (int)(rs % g.srcRPL);
  long orow = layer * g.outRPL + g.outOff + (long)r * g.rstride;
  float4 v = ((const float4*)g.in)[local];
  float vv[4] = {v.x, v.y, v.z, v.w};
  ushort h[4];
#pragma unroll
  for (int e = 0; e < 4; e++) h[e] = __half_as_ushort(__float2half_rn(vv[e]));
  uint2 hp = {(uint32_t)h[0] | ((uint32_t)h[1] << 16), (uint32_t)h[2] | ((uint32_t)h[3] << 16)};
  __half* ob = (__half*)g.out + orow * (long)g.K;
  *(uint2*)(ob + c) = hp;
}

// ---------------- pipelined fp16 tensor-core GEMM ----------------
// C[n,m] = sum_k A[n,k]*W[m,k], fp16 operands, fp32 accum.
// MODE 0: store fp32. 1: sigmoid where col<sigcut else store (fp32).
// MODE 2: += C (fp32). MODE 3: fused SwiGLU -> fp16 at col gc/2 (M=kDFF).
// MODE 4: store fp16.
#define BM 128
#define BN 128
#define BK 32
#define NST 3
#define LDSB 80  // bytes per smem row (40 elems)
#define STAGE_B ((BM + BN) * LDSB)  // 20480

template <int MODE>
__global__ void __launch_bounds__(256, 2)
gemm3(const __half* __restrict__ A, const __half* __restrict__ W,
      float* __restrict__ C, int M, int Kp, int sigcut) {
  extern __shared__ bf16 dynsmem[];
  uint32_t sbase = smem_u32(dynsmem);

  int tid = threadIdx.x;
  int lane = tid & 31, wid = tid >> 5;
  int wm = wid >> 2, wn = wid & 3;  // 2x4 warps, warp tile 64x32

  const __half* Ab = A + (size_t)(blockIdx.x * BM) * Kp;
  const __half* Wb = W + (size_t)(blockIdx.y * BN) * Kp;

  int r0 = tid >> 2, c0 = (tid & 3);
  int r1 = (tid + 256) >> 2, c1 = (tid & 3);

  float acc[4][4][4];
#pragma unroll
  for (int i = 0; i < 4; i++)
#pragma unroll
    for (int j = 0; j < 4; j++)
#pragma unroll
      for (int q = 0; q < 4; q++) acc[i][j][q] = 0.f;

  int KT = Kp / BK;

  int laneA = (wm * 64 + (lane & 7) + ((lane >> 3) & 1) * 8) * LDSB + ((lane >> 4)) * 16;
  int laneW = BM * LDSB + (wn * 32 + (lane & 7) + (lane >> 4) * 8) * LDSB +
              (((lane >> 3) & 1)) * 16;

#define ISSUE(stage, kt)                                                            \
  {                                                                                 \
    uint32_t sb = sbase + (uint32_t)(stage) * STAGE_B;                              \
    const __half* ga = Ab + (size_t)(kt) * BK;                                      \
    const __half* gw = Wb + (size_t)(kt) * BK;                                      \
    cp16(sb + r0 * LDSB + c0 * 16, ga + (size_t)r0 * Kp + c0 * 8);                  \
    cp16(sb + r1 * LDSB + c1 * 16, ga + (size_t)r1 * Kp + c1 * 8);                  \
    cp16(sb + BM * LDSB + r0 * LDSB + c0 * 16, gw + (size_t)r0 * Kp + c0 * 8);      \
    cp16(sb + BM * LDSB + r1 * LDSB + c1 * 16, gw + (size_t)r1 * Kp + c1 * 8);      \
  }

  ISSUE(0, 0); cp_commit();
  ISSUE(1, 1); cp_commit();

  for (int kt = 0; kt < KT; kt++) {
    cp_wait<1>();
    __syncthreads();
    int st = kt % NST;
    if (kt + 2 < KT) { ISSUE((kt + 2) % NST, kt + 2); }
    cp_commit();

    uint32_t stA = sbase + st * STAGE_B + laneA;
    uint32_t stW = sbase + st * STAGE_B + laneW;
#pragma unroll
    for (int kk = 0; kk < 2; kk++) {
      uint32_t b[8];
      ldm_x4(b, stW + kk * 32);
      ldm_x4(b + 4, stW + 16 * LDSB + kk * 32);
#pragma unroll
      for (int mt = 0; mt < 4; mt++) {
        uint32_t a[4];
        ldm_x4(a, stA + mt * 16 * LDSB + kk * 32);
#pragma unroll
        for (int nt = 0; nt < 4; nt++) mma_f16(acc[mt][nt], a, b + nt * 2);
      }
    }
  }
#undef ISSUE

  // epilogue
#pragma unroll
  for (int mt = 0; mt < 4; mt++) {
#pragma unroll
    for (int nt = 0; nt < 4; nt++) {
      int gr0 = blockIdx.x * BM + wm * 64 + mt * 16 + (lane >> 2);
      int gc = blockIdx.y * BN + wn * 32 + nt * 8 + ((lane & 3) << 1);
#pragma unroll
      for (int half = 0; half < 2; half++) {
        int gr = gr0 + half * 8;
        float v0 = acc[mt][nt][half * 2 + 0];
        float v1 = acc[mt][nt][half * 2 + 1];
        if (MODE == 3) {
          float y = (v0 / (1.f + expf(-v0))) * v1;
          __half* oh = (__half*)C;
          oh[(size_t)gr * M + (gc >> 1)] = __float2half_rn(y);
        } else if (MODE == 4) {
          __half* oh = (__half*)C;
          size_t off = (size_t)gr * M + gc;
          __half2 o2h = {__float2half_rn(v0), __float2half_rn(v1)};
          *(__half2*)&oh[off] = o2h;
        } else {
          size_t off = (size_t)gr * M + gc;
          if (MODE == 1) {
            if (gc < sigcut) {
              v0 = 1.f / (1.f + expf(-v0));
              v1 = 1.f / (1.f + expf(-v1));
            }
          } else if (MODE == 2) {
            float2 old = *(const float2*)&C[off];
            v0 += old.x; v1 += old.y;
          }
          float2 o2 = {v0, v1};
          *(float2*)&C[off] = o2;
        }
      }
    }
  }
}

// ---------------- split-K GEMM: gridDim.z slices of K, partial fp32 out -----
__global__ void __launch_bounds__(256, 2)
gemm_sk(const __half* __restrict__ A, const __half* __restrict__ W,
        float* __restrict__ P, int M, int Khalf, int stride) {
  extern __shared__ bf16 dynsmem[];
  uint32_t sbase = smem_u32(dynsmem);

  int tid = threadIdx.x;
  int lane = tid & 31, wid = tid >> 5;
  int wm = wid >> 2, wn = wid & 3;

  int koff = blockIdx.z * Khalf;
  const __half* Ab = A + (size_t)(blockIdx.x * BM) * stride + koff;
  const __half* Wb = W + (size_t)(blockIdx.y * BN) * stride + koff;
  float* Pb = P + (size_t)blockIdx.z * gridDim.x * BM * M;

  int r0 = tid >> 2, c0 = (tid & 3);
  int r1 = (tid + 256) >> 2, c1 = (tid & 3);

  float acc[4][4][4];
#pragma unroll
  for (int i = 0; i < 4; i++)
#pragma unroll
    for (int j = 0; j < 4; j++)
#pragma unroll
      for (int q = 0; q < 4; q++) acc[i][j][q] = 0.f;

  int KT = Khalf / BK;

  int laneA = (wm * 64 + (lane & 7) + ((lane >> 3) & 1) * 8) * LDSB + ((lane >> 4)) * 16;
  int laneW = BM * LDSB + (wn * 32 + (lane & 7) + (lane >> 4) * 8) * LDSB +
              (((lane >> 3) & 1)) * 16;

#define ISSUE2(stage, kt)                                                              \
  {                                                                                    \
    uint32_t sb = sbase + (uint32_t)(stage) * STAGE_B;                                 \
    const __half* ga = Ab + (size_t)(kt) * BK;                                         \
    const __half* gw = Wb + (size_t)(kt) * BK;                                         \
    cp16(sb + r0 * LDSB + c0 * 16, ga + (size_t)r0 * stride + c0 * 8);                 \
    cp16(sb + r1 * LDSB + c1 * 16, ga + (size_t)r1 * stride + c1 * 8);                 \
    cp16(sb + BM * LDSB + r0 * LDSB + c0 * 16, gw + (size_t)r0 * stride + c0 * 8);     \
    cp16(sb + BM * LDSB + r1 * LDSB + c1 * 16, gw + (size_t)r1 * stride + c1 * 8);     \
  }

  ISSUE2(0, 0); cp_commit();
  ISSUE2(1, 1); cp_commit();

  for (int kt = 0; kt < KT; kt++) {
    cp_wait<1>();
    __syncthreads();
    int st = kt % NST;
    if (kt + 2 < KT) { ISSUE2((kt + 2) % NST, kt + 2); }
    cp_commit();

    uint32_t stA = sbase + st * STAGE_B + laneA;
    uint32_t stW = sbase + st * STAGE_B + laneW;
#pragma unroll
    for (int kk = 0; kk < 2; kk++) {
      uint32_t b[8];
      ldm_x4(b, stW + kk * 32);
      ldm_x4(b + 4, stW + 16 * LDSB + kk * 32);
#pragma unroll
      for (int mt = 0; mt < 4; mt++) {
        uint32_t a[4];
        ldm_x4(a, stA + mt * 16 * LDSB + kk * 32);
#pragma unroll
        for (int nt = 0; nt < 4; nt++) mma_f16(acc[mt][nt], a, b + nt * 2);
      }
    }
  }
#undef ISSUE2

#pragma unroll
  for (int mt = 0; mt < 4; mt++) {
#pragma unroll
    for (int nt = 0; nt < 4; nt++) {
      int gr0 = blockIdx.x * BM + wm * 64 + mt * 16 + (lane >> 2);
      int gc = blockIdx.y * BN + wn * 32 + nt * 8 + ((lane & 3) << 1);
#pragma unroll
      for (int half = 0; half < 2; half++) {
        int gr = gr0 + half * 8;
        size_t off = (size_t)gr * M + gc;
        float2 o2 = {acc[mt][nt][half * 2 + 0], acc[mt][nt][half * 2 + 1]};
        *(float2*)&Pb[off] = o2;
      }
    }
  }
}

// ---------------- LayerNorm reduction core ----------------
__device__ __forceinline__ void ln_reduce2(float& s, float& ss) {
  int tid = threadIdx.x;
  __shared__ float shs[32], shss[32];
  for (int off = 16; off; off >>= 1) {
    s += __shfl_down_sync(0xffffffffu, s, off);
    ss += __shfl_down_sync(0xffffffffu, ss, off);
  }
  if ((tid & 31) == 0) { shs[tid >> 5] = s; shss[tid >> 5] = ss; }
  __syncthreads();
  if (tid < 32) {
    s = tid < 8 ? shs[tid] : 0.f;
    ss = tid < 8 ? shss[tid] : 0.f;
    for (int off = 4; off; off >>= 1) {
      s += __shfl_down_sync(0xffffffffu, s, off);
      ss += __shfl_down_sync(0xffffffffu, ss, off);
    }
    if (tid == 0) { shs[0] = s; shss[0] = ss; }
  }
  __syncthreads();
  s = shs[0]; ss = shss[0];
}

__global__ void ln_rows1h(const float* __restrict__ in, __half* __restrict__ out1,
                          const float* __restrict__ w, const float* __restrict__ bb) {
  size_t row = blockIdx.x;
  const float* x = in + row * kD;
  int tid = threadIdx.x;
  float s = 0.f, ss = 0.f;
  for (int i = tid; i < kD; i += 256) { float v = x[i]; s += v; ss += v * v; }
  ln_reduce2(s, ss);
  float mean = s / (float)kD;
  float var = ss / (float)kD - mean * mean;
  float rstd = rsqrtf(var + 1e-5f);
  __half* ob = out1 + row * kD;
  for (int i = tid; i < kD; i += 256) {
    float y = (x[i] - mean) * rstd * w[i] + bb[i];
    ob[i] = __float2half_rn(y);
  }
}

// fused: x += p0 + p1, then LayerNorm(x) -> fp16 out
__global__ void addln1h(const float* __restrict__ p, float* __restrict__ x,
                        const float* __restrict__ w, const float* __restrict__ bb,
                        __half* __restrict__ out1) {
  size_t row = blockIdx.x;
  int tid = threadIdx.x;
  const float* p0 = p + row * kD;
  const float* p1 = p + (size_t)kN * kD + row * kD;
  float* xr = x + row * kD;
  float v[4];
  float s = 0.f, ss = 0.f;
#pragma unroll
  for (int j = 0; j < 4; j++) {
    int i = tid + j * 256;
    float nv = xr[i] + (p0[i] + p1[i]);
    v[j] = nv;
    xr[i] = nv;
    s += nv; ss += nv * nv;
  }
  ln_reduce2(s, ss);
  float mean = s / (float)kD;
  float var = ss / (float)kD - mean * mean;
  float rstd = rsqrtf(var + 1e-5f);
  __half* ob = out1 + row * kD;
#pragma unroll
  for (int j = 0; j < 4; j++) {
    int i = tid + j * 256;
    float y = (v[j] - mean) * rstd * w[i] + bb[i];
    ob[i] = __float2half_rn(y);
  }
}

__global__ void embed_ln(const int* __restrict__ idx, const float* __restrict__ embed,
                         const float* __restrict__ w, const float* __restrict__ bb,
                         float* __restrict__ out) {
  size_t row = blockIdx.x;
  const float* x = embed + (size_t)idx[row] * kD;
  int tid = threadIdx.x;
  float s = 0.f, ss = 0.f;
  for (int i = tid; i < kD; i += 256) { float v = x[i]; s += v; ss += v * v; }
  ln_reduce2(s, ss);
  float mean = s / (float)kD;
  float var = ss / (float)kD - mean * mean;
  float rstd = rsqrtf(var + 1e-5f);
  float* o = out + row * kD;
  for (int i = tid; i < kD; i += 256)
    o[i] = (x[i] - mean) * rstd * w[i] + bb[i];
}

// ---------------- TimeMix decay scan (R13-proven) ----------------
#define TMCH 32
#define DGRP 8
__global__ void timemix2(const float* __restrict__ rkv, const float* __restrict__ decay_l,
                         float* __restrict__ out) {
  int b = blockIdx.x / (kD / DGRP);
  int dg = blockIdx.x % (kD / DGRP);
  int d = dg * DGRP + threadIdx.x;
  int chunk = threadIdx.y;
  const int clen = kT / TMCH;
  int t0 = chunk * clen;

  float dec = 1.f / (1.f + expf(-decay_l[d]));
  float logdec = logf(fmaxf(dec, 1e-7f));
  size_t base = (size_t)b * kT * 3 * kD;
  const float* rp = rkv + base + d;
  const float* kp = rkv + base + kD + d;
  const float* vp = rkv + base + 2 * kD + d;
  float* op = out + (size_t)b * kT * kD + d;

  float s = 0.f;
  for (int t = t0; t < t0 + clen; t++) {
    float scale = __expf((float)t * logdec);
    float denom = fmaxf(scale, 1e-10f);
    s += __fdividef(kp[(size_t)t * 3 * kD] * vp[(size_t)t * 3 * kD], denom);
  }
  __shared__ float cs[TMCH][DGRP];
  cs[chunk][threadIdx.x] = s;
  __syncthreads();
  float cum = 0.f;
  for (int c = 0; c < chunk; c++) cum += cs[c][threadIdx.x];
  for (int t = t0; t < t0 + clen; t++) {
    float scale = __expf((float)t * logdec);
    float denom = fmaxf(scale, 1e-10f);
    cum += __fdividef(kp[(size_t)t * 3 * kD] * vp[(size_t)t * 3 * kD], denom);
    op[(size_t)t * kD] = rp[(size_t)t * 3 * kD] * (cum * scale);
  }
}

// ---------------- GroupNorm(1,D) over (T,D) per batch (partials) -----------
__global__ void gn_reduce(const float* __restrict__ in) {
  const int CH = 64;
  int b = blockIdx.x / CH, chunk = blockIdx.x % CH;
  const int n = kT * kD / CH;
  const float* p = in + (size_t)b * kT * kD + (size_t)chunk * n;
  double s = 0.0, ss = 0.0;
  for (int i = threadIdx.x; i < n; i += blockDim.x) {
    double v = (double)p[i];
    s += v; ss += v * v;
  }
  __shared__ double sh1[32], sh2[32];
  for (int off = 16; off; off >>= 1) {
    s += __shfl_down_sync(0xffffffffu, s, off);
    ss += __shfl_down_sync(0xffffffffu, ss, off);
  }
  int tid = threadIdx.x;
  if ((tid & 31) == 0) { sh1[tid >> 5] = s; sh2[tid >> 5] = ss; }
  __syncthreads();
  int nw = (blockDim.x + 31) >> 5;
  if (tid < 32) {
    s = tid < nw ? sh1[tid] : 0.0;
    ss = tid < nw ? sh2[tid] : 0.0;
    for (int off = 16; off; off >>= 1) {
      s += __shfl_down_sync(0xffffffffu, s, off);
      ss += __shfl_down_sync(0xffffffffu, ss, off);
    }
    if (tid == 0) { g_gn_part[b][chunk][0] = s; g_gn_part[b][chunk][1] = ss; }
  }
}

// GN apply -> fp16 single A-layout (for Wotm GEMM)
__global__ void gn_apply1h(const float* __restrict__ in, const float* __restrict__ gw,
                           const float* __restrict__ gb, __half* __restrict__ out1) {
  int b = blockIdx.y;
  __shared__ float sh_m, sh_r;
  if (threadIdx.x == 0) {
    double s = 0.0, ss = 0.0;
    for (int c2 = 0; c2 < 64; c2++) { s += g_gn_part[b][c2][0]; ss += g_gn_part[b][c2][1]; }
    double inv = 1.0 / (double)(kT * kD);
    double m = s * inv;
    double var = ss * inv - m * m;
    sh_m = (float)m;
    sh_r = rsqrtf((float)var + 1e-5f);
  }
  __syncthreads();
  int idx = blockIdx.x * blockDim.x + threadIdx.x;
  int d = idx & (kD - 1);
  size_t row = (size_t)b * kT + (idx >> 10);
  float y = (in[(size_t)b * kT * kD + idx] - sh_m) * sh_r * gw[d] + gb[d];
  out1[row * kD + d] = __float2half_rn(y);
}

// ---------------- per-row logit stats (two-pass) ----------------
template <int HALF>
__global__ void rowstats(const void* __restrict__ logits, const int* __restrict__ targets,
                         float* __restrict__ lse, float* __restrict__ tgt,
                         int* __restrict__ amax, float* __restrict__ ent) {
  int row = blockIdx.x;
  int tid = threadIdx.x;
  const float* Lf = (const float*)logits + (size_t)row * kV;
  const __half* Lh = (const __half*)logits + (size_t)row * kV;

  __shared__ float svals[256];
  __shared__ int sidx[256];
  float m = -3.4e38f; int mi = 0;
  for (int i = tid; i < kV; i += 256) {
    float v = HALF ? __half2float(Lh[i]) : Lf[i];
    if (v > m) { m = v; mi = i; }
  }
  svals[tid] = m; sidx[tid] = mi;
  __syncthreads();
  for (int off = 128; off > 0; off >>= 1) {
    if (tid < off) {
      float v2 = svals[tid + off]; int i2 = sidx[tid + off];
      if (v2 > svals[tid] || (v2 == svals[tid] && i2 < sidx[tid])) { svals[tid] = v2; sidx[tid] = i2; }
    }
    __syncthreads();
  }
  float M = svals[0]; int MI = sidx[0];
  __syncthreads();
  float s = 0.f, t2 = 0.f;
  for (int i = tid; i < kV; i += 256) {
    float v = (HALF ? __half2float(Lh[i]) : Lf[i]) - M;
    float e = __expf(v);
    s += e; t2 += e * v;
  }
  svals[tid] = s; __syncthreads();
  for (int off = 128; off > 0; off >>= 1) { if (tid < off) svals[tid] += svals[tid + off]; __syncthreads(); }
  float S = svals[0]; __syncthreads();
  svals[tid] = t2; __syncthreads();
  for (int off = 128; off > 0; off >>= 1) { if (tid < off) svals[tid] += svals[tid + off]; __syncthreads(); }
  float T2 = svals[0];
  if (tid == 0) {
    lse[row] = M + logf(S);
    if (ent) ent[row] = logf(S) - T2 / S;
    amax[row] = MI;
    int tg = targets[row];
    tgt[row] = HALF ? __half2float(Lh[tg]) : Lf[tg];
  }
}

// ---------------- exit gate ----------------
__global__ void colmean1h(const __half* __restrict__ he1, float* __restrict__ hbar) {
  int d = blockIdx.x * blockDim.x + threadIdx.x;
  int b = blockIdx.y;
  float s = 0.f;
  const __half* p = he1 + (size_t)b * kT * kD;
  for (int t = 0; t < kT; t++) s += __half2float(p[(size_t)t * kD + d]);
  hbar[b * kD + d] = s / (float)kT;
}

__global__ void gate_kernel(const float* __restrict__ hbar, const float* __restrict__ w1,
                            const float* __restrict__ b1, const float* __restrict__ w2,
                            const float* __restrict__ b2, int j) {
  __shared__ float g[kB][64];
  int tid = threadIdx.x;
  if (tid < kB * 64) {
    int b = tid / 64, u = tid % 64;
    float s = 0.f;
    const float* hp = hbar + b * kD;
    const float* wp = w1 + (size_t)u * kD;
    for (int d = 0; d < kD; d++) s += hp[d] * wp[d];
    g[b][u] = fmaxf(s + b1[u], 0.f);
  }
  __syncthreads();
  if (tid < kB) {
    float s = 0.f;
    for (int u = 0; u < 64; u++) s += g[tid][u] * w2[u];
    g_conf[j * kB + tid] = 1.f / (1.f + expf(-(s + b2[0])));
  }
}

// ---------------- loss assembly ----------------
__global__ void loss_kernel(float* __restrict__ loss_out) {
  int tid = threadIdx.x;
  float ce_f = 0.f, ce_e[2] = {0.f, 0.f};
  float ag[2][2] = {{0.f, 0.f}, {0.f, 0.f}};
  float oc[2] = {0.f, 0.f};
  const float maxent = logf((float)kV);
  for (int r = tid; r < kN; r += 256) {
    int fp = g_amax_f[r];
    ce_f += g_lse_f[r] - g_tgt_f[r];
    int b = r / kT;
#pragma unroll
    for (int j = 0; j < 2; j++) {
      ce_e[j] += g_lse_e[j * kN + r] - g_tgt_e[j * kN + r];
      int ep = g_amax_e[j * kN + r];
      if (ep == fp) ag[j][b] += 1.f;
      else oc[j] += (1.f - g_ent_e[j * kN + r] / maxent);
    }
  }
  __shared__ float sh[256];
  float vals[9] = {ce_f, ce_e[0], ce_e[1], ag[0][0], ag[0][1], ag[1][0], ag[1][1], oc[0], oc[1]};
  float red[9];
#pragma unroll
  for (int q = 0; q < 9; q++) {
    sh[tid] = vals[q];
    __syncthreads();
    for (int off = 128; off > 0; off >>= 1) { if (tid < off) sh[tid] += sh[tid + off]; __syncthreads(); }
    red[q] = sh[0];
    __syncthreads();
  }
  if (tid == 0) {
    const float w[2] = {0.3f, 0.5f};
    float loss = red[0] / (float)kN;
    for (int j = 0; j < 2; j++) {
      loss += w[j] * (red[1 + j] / (float)kN);
      float bce = 0.f;
      for (int b = 0; b < kB; b++) {
        float agree = red[3 + j * 2 + b] / (float)kT;
        float c = fminf(fmaxf(g_conf[j * kB + b], 1e-7f), 1.f - 1e-7f);
        bce += -(agree * logf(c) + (1.f - agree) * logf(1.f - c));
      }
      loss += 0.5f * (bce / (float)kB);
      loss += 0.1f * (red[7 + j] / (float)kN);
    }
    loss_out[0] = loss;
  }
}

// ---------------- host orchestration ----------------
#define DSMEM (NST * STAGE_B)  // 61440

extern "C" void kernel_launch(void* const* d_in, const int* in_sizes, int n_in,
                              void* d_out, int out_size) {
  const int* idx = (const int*)d_in[0];
  const int* targets = (const int*)d_in[1];
  const float* embed = (const float*)d_in[2];
  const float* ln_in_w = (const float*)d_in[3];
  const float* ln_in_b = (const float*)d_in[4];
  const float* Wr = (const float*)d_in[5];
  const float* Wk = (const float*)d_in[6];
  const float* Wv = (const float*)d_in[7];
  const float* Wo_tm = (const float*)d_in[8];
  const float* decay = (const float*)d_in[9];
  const float* gn_w = (const float*)d_in[10];
  const float* gn_b = (const float*)d_in[11];
  const float* ln1_w = (const float*)d_in[12];
  const float* ln1_b = (const float*)d_in[13];
  const float* ln2_w = (const float*)d_in[14];
  const float* ln2_b = (const float*)d_in[15];
  const float* W1 = (const float*)d_in[16];
  const float* W2 = (const float*)d_in[17];
  const float* Wo_cm = (const float*)d_in[18];
  const float* ln_out_w = (const float*)d_in[19];
  const float* ln_out_b = (const float*)d_in[20];
  const float* exit_ln_w = (const float*)d_in[21];
  const float* exit_ln_b = (const float*)d_in[22];
  const float* exit_head = (const float*)d_in[23];
  const float* gate_w1 = (const float*)d_in[24];
  const float* gate_b1 = (const float*)d_in[25];
  const float* gate_w2 = (const float*)d_in[26];
  const float* gate_b2 = (const float*)d_in[27];
  float* out = (float*)d_out;

  float *xp, *rkvp, *attp, *partp, *elp, *hbarp;
  float *lse_f, *tgt_f, *lse_e, *tgt_e, *ent_e;
  int *amax_f, *amax_e;
  __half *h1p, *ff2hp, *Wrkvh, *Wotmh, *W123h, *Wocmh, *embedh, *exith;
  cudaGetSymbolAddress((void**)&xp, g_x);
  cudaGetSymbolAddress((void**)&rkvp, g_rkv);
  cudaGetSymbolAddress((void**)&attp, g_att);
  cudaGetSymbolAddress((void**)&partp, g_part);
  cudaGetSymbolAddress((void**)&elp, g_elog);
  cudaGetSymbolAddress((void**)&hbarp, g_hbar);
  cudaGetSymbolAddress((void**)&lse_f, g_lse_f);
  cudaGetSymbolAddress((void**)&tgt_f, g_tgt_f);
  cudaGetSymbolAddress((void**)&amax_f, g_amax_f);
  cudaGetSymbolAddress((void**)&lse_e, g_lse_e);
  cudaGetSymbolAddress((void**)&tgt_e, g_tgt_e);
  cudaGetSymbolAddress((void**)&ent_e, g_ent_e);
  cudaGetSymbolAddress((void**)&amax_e, g_amax_e);
  cudaGetSymbolAddress((void**)&h1p, g_h1);
  cudaGetSymbolAddress((void**)&ff2hp, g_ff2h);
  cudaGetSymbolAddress((void**)&Wrkvh, g_Wrkvh);
  cudaGetSymbolAddress((void**)&Wotmh, g_Wotmh);
  cudaGetSymbolAddress((void**)&W123h, g_W123h);
  cudaGetSymbolAddress((void**)&Wocmh, g_Wocmh);
  cudaGetSymbolAddress((void**)&embedh, g_embedh);
  cudaGetSymbolAddress((void**)&exith, g_exith);

  cudaFuncSetAttribute((const void*)gemm3<0>, cudaFuncAttributeMaxDynamicSharedMemorySize, DSMEM);
  cudaFuncSetAttribute((const void*)gemm3<1>, cudaFuncAttributeMaxDynamicSharedMemorySize, DSMEM);
  cudaFuncSetAttribute((const void*)gemm3<3>, cudaFuncAttributeMaxDynamicSharedMemorySize, DSMEM);
  cudaFuncSetAttribute((const void*)gemm3<4>, cudaFuncAttributeMaxDynamicSharedMemorySize, DSMEM);
  cudaFuncSetAttribute((const void*)gemm_sk, cudaFuncAttributeMaxDynamicSharedMemorySize, DSMEM);

  dim3 g_rkvg(kN / BM, (3 * kD) / BN);     // (16,24)
  dim3 g_ddsk(kN / BM, kD / BN, 2);        // (16,8,2) split-K
  dim3 g_w12(kN / BM, (2 * kDFF) / BN);    // (16,64)
  dim3 g_vg(kN / BM, kV / BN);             // (16,250)

  const long L4 = 0x7fffffffffffffffL;

  // ---- launch #1: fp16 TimeMix weight conversion (single-term) ----
  {
    ConvArgs a1;
    long t = (long)kL * kD * kD / 4;
    a1.s[0] = {Wr, Wrkvh, kD, kD, 3 * kD, 0, 2, 1, t};
    a1.s[1] = {Wk, Wrkvh, kD, kD, 3 * kD, kD, 2, 1, 2 * t};
    a1.s[2] = {Wv, Wrkvh, kD, kD, 3 * kD, 2 * kD, 2, 1, 3 * t};
    a1.s[3] = {Wo_tm, Wotmh, kD, kL * kD, kL * kD, 0, 2, 1, 4 * t};
    conv_multi<<<(unsigned)((4 * t + 255) / 256), 256>>>(a1, 4 * t);
  }

  // ---- launches #2-#4: embed_ln, ln1(l0), rkv GEMM(l0) ----
  embed_ln<<<kN, 256>>>(idx, embed, ln_in_w, ln_in_b, xp);
  ln_rows1h<<<kN, 256>>>(xp, h1p, ln1_w, ln1_b);
  gemm3<1><<<g_rkvg, 256, DSMEM>>>(h1p, Wrkvh, rkvp, 3 * kD, kD, kD);

  // ---- remaining weight conversions ----
  {
    ConvArgs a2;  // fp16 single ChannelMix weights (W1/W2 row-interleaved)
    long u = (long)kL * kDFF * kD / 4;
    a2.s[0] = {W1, W123h, kD, kDFF, 2 * kDFF, 0, 2, 2, u};
    a2.s[1] = {W2, W123h, kD, kDFF, 2 * kDFF, 1, 2, 2, 2 * u};
    a2.s[2] = {Wo_cm, Wocmh, kDFF, kL * kD, kL * kD, 0, 2, 1, 3 * u};
    a2.s[3] = {nullptr, nullptr, 4, 1, 1, 0, 2, 1, L4};
    conv_multi<<<(unsigned)((3 * u + 255) / 256), 256>>>(a2, 3 * u);
    ConvArgs a3;  // fp16 single vocab weights
    long e1 = (long)kV * kD / 4, e2 = 2L * kV * kD / 4;
    a3.s[0] = {embed, embedh, kD, kV, kV, 0, 2, 1, e1};
    a3.s[1] = {exit_head, exith, kD, 2 * kV, 2 * kV, 0, 2, 1, e1 + e2};
    a3.s[2] = {nullptr, nullptr, 4, 1, 1, 0, 2, 1, L4};
    a3.s[3] = {nullptr, nullptr, 4, 1, 1, 0, 2, 1, L4};
    conv_multi<<<(unsigned)((e1 + e2 + 255) / 256), 256>>>(a3, e1 + e2);
  }

  for (int i = 0; i < kL; i++) {
    // --- TimeMix ---
    // ln1 for this layer: layer 0 hoisted above; layers 4,8 launched after the
    // exit block below; all others were fused into the previous layer's addln.
    if (i == 4 || i == 8) {
      ln_rows1h<<<kN, 256>>>(xp, h1p, ln1_w + i * kD, ln1_b + i * kD);
    }
    if (i > 0) {
      gemm3<1><<<g_rkvg, 256, DSMEM>>>(h1p, Wrkvh + (size_t)i * 3 * kD * kD, rkvp,
                                       3 * kD, kD, kD);
    }
    timemix2<<<kB * (kD / DGRP), dim3(DGRP, TMCH)>>>(rkvp, decay + i * kD, attp);
    gn_reduce<<<kB * 64, 256>>>(attp);
    gn_apply1h<<<dim3(kT * kD / 256, kB), 256>>>(attp, gn_w + i * kD, gn_b + i * kD, h1p);
    gemm_sk<<<g_ddsk, 256, DSMEM>>>(h1p, Wotmh + (size_t)i * kD * kD, partp,
                                    kD, 512, kD);
    // fused: x += parts; ln2(x) -> h1
    addln1h<<<kN, 256>>>(partp, xp, ln2_w + i * kD, ln2_b + i * kD, h1p);
    // --- ChannelMix (single-term fp16, fused SwiGLU epilogue) ---
    gemm3<3><<<g_w12, 256, DSMEM>>>(h1p, W123h + (size_t)i * 2 * kDFF * kD,
                                    (float*)ff2hp, kDFF, kD, 0);
    gemm_sk<<<g_ddsk, 256, DSMEM>>>(ff2hp, Wocmh + (size_t)i * kD * kDFF, partp,
                                    kD, 2048, kDFF);
    // fused: x += parts; next-LN(x) -> h1
    if (i == 3 || i == 7) {
      int j = (i == 3) ? 0 : 1;
      addln1h<<<kN, 256>>>(partp, xp, exit_ln_w + j * kD, exit_ln_b + j * kD, h1p);
      gemm3<4><<<g_vg, 256, DSMEM>>>(h1p, exith + (size_t)j * kV * kD, elp, kV, kD, 0);
      rowstats<1><<<kN, 256>>>(elp, targets, lse_e + j * kN, tgt_e + j * kN,
                               amax_e + j * kN, ent_e + j * kN);
      colmean1h<<<dim3(kD / 256, kB), 256>>>(h1p, hbarp);
      gate_kernel<<<1, 128>>>(hbarp, gate_w1 + (size_t)j * 64 * kD, gate_b1 + j * 64,
                              gate_w2 + j * 64, gate_b2 + j, j);
    } else if (i < kL - 1) {
      addln1h<<<kN, 256>>>(partp, xp, ln1_w + (i + 1) * kD, ln1_b + (i + 1) * kD, h1p);
    } else {
      addln1h<<<kN, 256>>>(partp, xp, ln_out_w, ln_out_b, h1p);
    }
  }

  // final tied head (fp32 logits into d_out; ln_out already applied by addln)
  gemm3<0><<<g_vg, 256, DSMEM>>>(h1p, embedh, out, kV, kD, 0);
  rowstats<0><<<kN, 256>>>(out, targets, lse_f, tgt_f, amax_f, (float*)nullptr);
  loss_kernel<<<1, 256>>>(out + (size_t)kN * kV);
}